// round 8
// baseline (speedup 1.0000x reference)
#include <cuda_runtime.h>
#include <math.h>

// ---------------- scratch (device globals; no allocation) ----------------
__device__ float g_t1[64*16*128*128];   // conv1 raw out
__device__ float g_t3[64*16*128*128];   // convT1 raw out
__device__ float g_t2[64*4*64*64];      // conv2 out
__device__ float g_di[64*4*64*64];      // post-VQ 1x1 out
__device__ float g_partA[1024*32];
__device__ float g_partF[1024*32];
__device__ float g_partC[256*8];
__device__ float g_partE[1024];
__device__ float g_partH[4096];
__device__ float g_bn1[32];  // scale[16], shift[16]
__device__ float g_bn2[8];
__device__ float g_bn3[32];
__device__ unsigned int g_c1, g_c2, g_c3, g_c4;   // zero-init; reset by last block

__device__ __forceinline__ float warp_sum(float v){
#pragma unroll
  for (int o = 16; o > 0; o >>= 1) v += __shfl_down_sync(0xffffffffu, v, o);
  return v;
}

// Deterministic finalize of [nblk][32] partials (16 channels) into bn[32].
// Runs in ONE block of 256 threads; fixed assignment + fixed tree order.
__device__ void bn_finalize32(const float* part, int nblk, float* bn,
                              const float* g, const float* be, double invN,
                              int tid){
  __shared__ double ssf[16], qqf[16];
  int c = tid >> 4;           // 16 threads per channel
  int sub = tid & 15;
  double s = 0.0, q = 0.0;
  for (int i = sub; i < nblk; i += 16){
    s += (double)part[i*32 + c];
    q += (double)part[i*32 + 16 + c];
  }
  // reduce 16 lanes within half-warp (lanes of same channel are contiguous)
#pragma unroll
  for (int o = 8; o > 0; o >>= 1){
    s += __shfl_down_sync(0xffffffffu, s, o, 16);
    q += __shfl_down_sync(0xffffffffu, q, o, 16);
  }
  if (sub == 0){ ssf[c] = s; qqf[c] = q; }
  __syncthreads();
  if (tid < 16){
    double S = ssf[tid], Q = qqf[tid];
    double mean = S*invN;
    double var  = Q*invN - mean*mean;
    float scale = (float)((double)g[tid] / sqrt(var + 1e-5));
    bn[tid] = scale;
    bn[16 + tid] = be[tid] - (float)mean * scale;
  }
}

// ---------------- K1: conv1 (1->16, k4 s2 p1) + store t1 + BN1 partials + BN1 finalize ----------------
// grid (4,4,64), block (32,8). warp = oc pair, lane = column, walk 32 rows.
__global__ void k_conv1(const float* __restrict__ x, const float* __restrict__ w1,
                        const float* __restrict__ b1,
                        const float* __restrict__ g1, const float* __restrict__ be1){
  __shared__ float s_in[66*68];
  __shared__ int s_last;
  const int bz = blockIdx.z;
  const int ox0 = blockIdx.x*32, oy0 = blockIdx.y*32;
  const int w = threadIdx.y, tx = threadIdx.x;
  const int tid = w*32 + tx;
  const int oc0 = 2*w, oc1 = 2*w + 1;
  float wr0[16], wr1[16];
#pragma unroll
  for (int j = 0; j < 16; j++){ wr0[j] = w1[oc0*16 + j]; wr1[j] = w1[oc1*16 + j]; }
  const float bb0 = b1[oc0], bb1 = b1[oc1];
  const float* xb = x + (size_t)bz*65536;
  for (int j = tid; j < 66*66; j += 256){
    int r = j/66, c = j - r*66;
    int gr = oy0*2 - 1 + r, gc = ox0*2 - 1 + c;
    float v = 0.f;
    if ((unsigned)gr < 256u && (unsigned)gc < 256u) v = xb[gr*256 + gc];
    s_in[r*68 + c] = v;
  }
  __syncthreads();
  float s0 = 0.f, q0 = 0.f, s1 = 0.f, q1 = 0.f;
  float* o0 = g_t1 + (size_t)bz*262144 + (size_t)oc0*16384 + (oy0)*128 + ox0 + tx;
  float* o1 = o0 + 16384;
  float r0[4], r1[4];
  {
    float2 u0 = *(const float2*)&s_in[0*68 + 2*tx];
    float2 u1 = *(const float2*)&s_in[0*68 + 2*tx + 2];
    float2 v0 = *(const float2*)&s_in[1*68 + 2*tx];
    float2 v1 = *(const float2*)&s_in[1*68 + 2*tx + 2];
    r0[0]=u0.x; r0[1]=u0.y; r0[2]=u1.x; r0[3]=u1.y;
    r1[0]=v0.x; r1[1]=v0.y; r1[2]=v1.x; r1[3]=v1.y;
  }
#pragma unroll 4
  for (int y = 0; y < 32; y++){
    float r2[4], r3[4];
    {
      float2 u0 = *(const float2*)&s_in[(2*y+2)*68 + 2*tx];
      float2 u1 = *(const float2*)&s_in[(2*y+2)*68 + 2*tx + 2];
      float2 v0 = *(const float2*)&s_in[(2*y+3)*68 + 2*tx];
      float2 v1 = *(const float2*)&s_in[(2*y+3)*68 + 2*tx + 2];
      r2[0]=u0.x; r2[1]=u0.y; r2[2]=u1.x; r2[3]=u1.y;
      r3[0]=v0.x; r3[1]=v0.y; r3[2]=v1.x; r3[3]=v1.y;
    }
    float a0 = bb0, a1 = bb1;
#pragma unroll
    for (int j = 0; j < 4; j++){
      a0 = fmaf(r0[j], wr0[j],    a0);  a1 = fmaf(r0[j], wr1[j],    a1);
      a0 = fmaf(r1[j], wr0[4+j],  a0);  a1 = fmaf(r1[j], wr1[4+j],  a1);
      a0 = fmaf(r2[j], wr0[8+j],  a0);  a1 = fmaf(r2[j], wr1[8+j],  a1);
      a0 = fmaf(r3[j], wr0[12+j], a0);  a1 = fmaf(r3[j], wr1[12+j], a1);
    }
    o0[y*128] = a0;  o1[y*128] = a1;
    s0 += a0; q0 = fmaf(a0, a0, q0);
    s1 += a1; q1 = fmaf(a1, a1, q1);
#pragma unroll
    for (int j = 0; j < 4; j++){ r0[j] = r2[j]; r1[j] = r3[j]; }
  }
  s0 = warp_sum(s0); q0 = warp_sum(q0);
  s1 = warp_sum(s1); q1 = warp_sum(q1);
  const int blk = (bz*4 + blockIdx.y)*4 + blockIdx.x;
  if (tx == 0){
    g_partA[blk*32 + oc0] = s0;
    g_partA[blk*32 + oc1] = s1;
    g_partA[blk*32 + 16 + oc0] = q0;
    g_partA[blk*32 + 16 + oc1] = q1;
  }
  __syncthreads();
  if (tid == 0){
    __threadfence();
    s_last = (atomicAdd(&g_c1, 1u) == 1023u);
  }
  __syncthreads();
  if (s_last){
    __threadfence();
    bn_finalize32(g_partA, 1024, g_bn1, g1, be1, 1.0/1048576.0, tid);
    if (tid == 0) g_c1 = 0;
  }
}

// ---------------- K2: BN1+ReLU + conv2 (16->4, k4 s2 p1) + BN2 partials + BN2 finalize ----------------
// grid (2,2,64), block (32,8). 32x32 t2 tile, 4-channel staged input (dynamic smem 71.8 KB).
__global__ void k_conv2(const float* __restrict__ w2, const float* __restrict__ b2,
                        const float* __restrict__ g2, const float* __restrict__ be2){
  extern __shared__ float s_in[];     // 4 * 66*68 floats
  __shared__ float s_w2[1024];
  __shared__ float s_bn[32];
  __shared__ float s_red[8*8];
  __shared__ int s_last;
  const int bz = blockIdx.z;
  const int ox0 = blockIdx.x*32, oy0 = blockIdx.y*32;
  const int ty = threadIdx.y, tx = threadIdx.x;
  const int tid = ty*32 + tx;
  for (int j = tid; j < 1024; j += 256) s_w2[j] = w2[j];
  if (tid < 32) s_bn[tid] = g_bn1[tid];
  float acc[4][4];
#pragma unroll
  for (int o = 0; o < 4; o++){
    float bo = b2[o];
#pragma unroll
    for (int k = 0; k < 4; k++) acc[o][k] = bo;
  }
  const float* t1b = g_t1 + (size_t)bz*262144;
  for (int st = 0; st < 4; st++){
    __syncthreads();
#pragma unroll
    for (int c4 = 0; c4 < 4; c4++){
      int c = st*4 + c4;
      float sc = s_bn[c], sh = s_bn[16+c];
      const float* inp = t1b + c*16384;
      for (int j = tid; j < 66*66; j += 256){
        int r = j/66, cc = j - r*66;
        int gr = 2*oy0 - 1 + r, gc = 2*ox0 - 1 + cc;
        float v = 0.f;
        if ((unsigned)gr < 128u && (unsigned)gc < 128u)
          v = fmaxf(fmaf(inp[gr*128 + gc], sc, sh), 0.f);
        s_in[c4*4488 + r*68 + cc] = v;
      }
    }
    __syncthreads();
#pragma unroll
    for (int c4 = 0; c4 < 4; c4++){
      int c = st*4 + c4;
      const float* sp = s_in + c4*4488;
#pragma unroll
      for (int ky = 0; ky < 4; ky++){
        float wk[4][4];
#pragma unroll
        for (int o = 0; o < 4; o++)
#pragma unroll
          for (int kx = 0; kx < 4; kx++)
            wk[o][kx] = s_w2[((o*16 + c)*4 + ky)*4 + kx];
#pragma unroll
        for (int k = 0; k < 4; k++){
          int rb = (2*(ty + 8*k) + ky)*68 + 2*tx;
          float2 va = *(const float2*)&sp[rb];
          float2 vb = *(const float2*)&sp[rb + 2];
#pragma unroll
          for (int o = 0; o < 4; o++){
            acc[o][k] = fmaf(va.x, wk[o][0], acc[o][k]);
            acc[o][k] = fmaf(va.y, wk[o][1], acc[o][k]);
            acc[o][k] = fmaf(vb.x, wk[o][2], acc[o][k]);
            acc[o][k] = fmaf(vb.y, wk[o][3], acc[o][k]);
          }
        }
      }
    }
  }
  float st8[8];
#pragma unroll
  for (int v = 0; v < 8; v++) st8[v] = 0.f;
  float* outb = g_t2 + bz*16384;
#pragma unroll
  for (int k = 0; k < 4; k++){
    int off = (oy0 + ty + 8*k)*64 + ox0 + tx;
#pragma unroll
    for (int o = 0; o < 4; o++){
      float a = acc[o][k];
      outb[o*4096 + off] = a;
      st8[o] += a;
      st8[4+o] = fmaf(a, a, st8[4+o]);
    }
  }
  int lane = tid & 31, warp = tid >> 5;
#pragma unroll
  for (int v = 0; v < 8; v++){
    float r = warp_sum(st8[v]);
    if (lane == 0) s_red[warp*8 + v] = r;
  }
  __syncthreads();
  const int blk = (bz*2 + blockIdx.y)*2 + blockIdx.x;
  if (tid < 8){
    float t = 0.f;
#pragma unroll
    for (int w = 0; w < 8; w++) t += s_red[w*8 + tid];
    g_partC[blk*8 + tid] = t;
  }
  __syncthreads();
  if (tid == 0){
    __threadfence();
    s_last = (atomicAdd(&g_c2, 1u) == 255u);
  }
  __syncthreads();
  if (s_last){
    __threadfence();
    // BN2 finalize: partC [256][8], 4 channels
    __shared__ double ss[8], qq[8];
    for (int c = 0; c < 4; c++){
      double s = (double)g_partC[tid*8 + c];
      double q = (double)g_partC[tid*8 + 4 + c];
#pragma unroll
      for (int o = 16; o > 0; o >>= 1){
        s += __shfl_down_sync(0xffffffffu, s, o);
        q += __shfl_down_sync(0xffffffffu, q, o);
      }
      if (lane == 0){ ss[warp] = s; qq[warp] = q; }
      __syncthreads();
      if (tid == 0){
        double S = 0.0, Q = 0.0;
#pragma unroll
        for (int w = 0; w < 8; w++){ S += ss[w]; Q += qq[w]; }
        const double invN = 1.0/262144.0;
        double mean = S*invN;
        double var  = Q*invN - mean*mean;
        float scale = (float)((double)g2[c] / sqrt(var + 1e-5));
        g_bn2[c] = scale;
        g_bn2[4 + c] = be2[c] - (float)mean * scale;
      }
      __syncthreads();
    }
    if (tid == 0) g_c2 = 0;
  }
}

// ---------------- K3: BN2+ReLU + pre1x1 + VQ + loss + post1x1 ----------------
__global__ void k_vq(const float* __restrict__ wpre, const float* __restrict__ bpre,
                     const float* __restrict__ emb,
                     const float* __restrict__ wpost, const float* __restrict__ bpost){
  __shared__ float s_e[128];
  __shared__ float s_ee[64];
  __shared__ float s_red[8];
  int tid = threadIdx.x;
  if (tid < 128) s_e[tid] = emb[tid];
  __syncthreads();
  if (tid < 64) s_ee[tid] = s_e[2*tid]*s_e[2*tid] + s_e[2*tid+1]*s_e[2*tid+1];
  __syncthreads();
  int i = blockIdx.x*256 + tid;
  int b = i >> 12, p = i & 4095;
  const float* tb = g_t2 + b*16384 + p;
  float h0 = fmaxf(fmaf(tb[0],     g_bn2[0], g_bn2[4]), 0.f);
  float h1 = fmaxf(fmaf(tb[4096],  g_bn2[1], g_bn2[5]), 0.f);
  float h2 = fmaxf(fmaf(tb[8192],  g_bn2[2], g_bn2[6]), 0.f);
  float h3 = fmaxf(fmaf(tb[12288], g_bn2[3], g_bn2[7]), 0.f);
  float z0 = bpre[0] + wpre[0]*h0 + wpre[1]*h1 + wpre[2]*h2 + wpre[3]*h3;
  float z1 = bpre[1] + wpre[4]*h0 + wpre[5]*h1 + wpre[6]*h2 + wpre[7]*h3;
  float zz = z0*z0 + z1*z1;
  float best = 3.402823466e38f; int bi = 0;
  for (int k = 0; k < 64; k++){
    float d = zz - 2.f*(z0*s_e[2*k] + z1*s_e[2*k+1]) + s_ee[k];
    if (d < best){ best = d; bi = k; }
  }
  float q0 = s_e[2*bi], q1 = s_e[2*bi+1];
  float l = (q0 - z0)*(q0 - z0) + (q1 - z1)*(q1 - z1);
  float qs0 = z0 + (q0 - z0), qs1 = z1 + (q1 - z1);
  float* db = g_di + b*16384 + p;
#pragma unroll
  for (int o = 0; o < 4; o++)
    db[o*4096] = bpost[o] + wpost[2*o]*qs0 + wpost[2*o+1]*qs1;
  int lane = tid & 31, warp = tid >> 5;
  float r = warp_sum(l);
  if (lane == 0) s_red[warp] = r;
  __syncthreads();
  if (tid == 0){
    float t = 0.f;
#pragma unroll
    for (int w = 0; w < 8; w++) t += s_red[w];
    g_partE[blockIdx.x] = t;
  }
}

// ---------------- K4: convT1 (4->16, k4 s2 p1) + store t3 + BN3 partials + BN3 finalize ----------------
// grid (4,4,64), block (32,16). warp = oc, lane = column, row-pair walk.
__global__ void k_convt1(const float* __restrict__ wd1, const float* __restrict__ bd1,
                         const float* __restrict__ g3, const float* __restrict__ be3){
  __shared__ float s_in[4*324];
  __shared__ int s_last;
  const int bz = blockIdx.z;
  const int ox0 = blockIdx.x*32, oy0 = blockIdx.y*32;
  const int oc = threadIdx.y, tx = threadIdx.x;
  const int tid = oc*32 + tx;
  const int kxA = (tx & 1) ? 2 : 3;
  const int kxB = (tx & 1) ? 0 : 1;
  float wA[4][4], wB[4][4];
#pragma unroll
  for (int c = 0; c < 4; c++)
#pragma unroll
    for (int ky = 0; ky < 4; ky++){
      wA[c][ky] = wd1[c*256 + oc*16 + ky*4 + kxA];
      wB[c][ky] = wd1[c*256 + oc*16 + ky*4 + kxB];
    }
  const float bb = bd1[oc];
  const int iyb = oy0/2 - 1, ixb = ox0/2 - 1;
  const float* inb = g_di + bz*16384;
  for (int j = tid; j < 1296; j += 512){
    int c = j/324, rem = j - c*324, r = rem/18, cc = rem - r*18;
    int iy = iyb + r, ix = ixb + cc;
    float v = 0.f;
    if ((unsigned)iy < 64u && (unsigned)ix < 64u) v = inb[c*4096 + iy*64 + ix];
    s_in[c*324 + rem] = v;
  }
  __syncthreads();
  const int lx = ((tx + 1) >> 1) + 1;
  float s = 0.f, q = 0.f;
  float* ob = g_t3 + (size_t)bz*262144 + (size_t)oc*16384 + oy0*128 + ox0 + tx;
#pragma unroll 2
  for (int a = 0; a <= 16; a++){
    int ly = a + 1;
    float accO = bb, accE = bb;
#pragma unroll
    for (int c = 0; c < 4; c++){
      const float* sp = s_in + c*324;
      float vA0 = sp[(ly-1)*18 + lx-1];
      float vA1 = sp[(ly-1)*18 + lx];
      float vB0 = sp[ly*18 + lx-1];
      float vB1 = sp[ly*18 + lx];
      accO = fmaf(vA0, wA[c][2], accO);
      accO = fmaf(vA1, wB[c][2], accO);
      accO = fmaf(vB0, wA[c][0], accO);
      accO = fmaf(vB1, wB[c][0], accO);
      accE = fmaf(vA0, wA[c][3], accE);
      accE = fmaf(vA1, wB[c][3], accE);
      accE = fmaf(vB0, wA[c][1], accE);
      accE = fmaf(vB1, wB[c][1], accE);
    }
    if (a >= 1){                       // y = 2a-1 (odd)
      ob[(2*a - 1)*128] = accO;
      s += accO; q = fmaf(accO, accO, q);
    }
    if (a <= 15){                      // y = 2a (even)
      ob[(2*a)*128] = accE;
      s += accE; q = fmaf(accE, accE, q);
    }
  }
  s = warp_sum(s); q = warp_sum(q);
  const int blk = (bz*4 + blockIdx.y)*4 + blockIdx.x;
  if (tx == 0){
    g_partF[blk*32 + oc] = s;
    g_partF[blk*32 + 16 + oc] = q;
  }
  __syncthreads();
  if (tid == 0){
    __threadfence();
    s_last = (atomicAdd(&g_c3, 1u) == 1023u);
  }
  __syncthreads();
  if (s_last){
    __threadfence();
    if (tid < 256)
      bn_finalize32(g_partF, 1024, g_bn3, g3, be3, 1.0/1048576.0, tid);
    if (tid == 0) g_c3 = 0;
  }
}

// ---------------- K5: BN3+ReLU + convT2 (16->1) + tanh + recon + total loss ----------------
// grid (8,8,64), block (32,8). Parity-resolved weights in registers.
__global__ void k_convt2(const float* __restrict__ x, const float* __restrict__ wd2,
                         const float* __restrict__ bd2, float* __restrict__ out,
                         float* __restrict__ out_loss){
  __shared__ float s_t3[16*324];
  __shared__ float s_w[256];
  __shared__ float s_bn[32];
  __shared__ float s_red[8];
  __shared__ int s_last;
  const int bz = blockIdx.z;
  const int ox0 = blockIdx.x*32, oy0 = blockIdx.y*32;
  const int ty = threadIdx.y, tx = threadIdx.x;
  const int tid = ty*32 + tx;
  s_w[tid] = wd2[tid];
  if (tid < 32) s_bn[tid] = g_bn3[tid];
  const float bd = bd2[0];
  __syncthreads();
  const int tyb = oy0/2 - 1, txb = ox0/2 - 1;
  const float* inb = g_t3 + (size_t)bz*262144;
  for (int j = tid; j < 16*324; j += 256){
    int c = j/324, rem = j - c*324, r = rem/18, cc = rem - r*18;
    int iy = tyb + r, ix = txb + cc;
    float v = 0.f;
    if ((unsigned)iy < 128u && (unsigned)ix < 128u)
      v = fmaxf(fmaf(inb[c*16384 + iy*128 + ix], s_bn[c], s_bn[16+c]), 0.f);
    s_t3[c*324 + rem] = v;
  }
  __syncthreads();
  const int kyA = (ty & 1) ? 2 : 3, kyB = (ty & 1) ? 0 : 1;
  const int kxA = (tx & 1) ? 2 : 3, kxB = (tx & 1) ? 0 : 1;
  float wAA[16], wAB[16], wBA[16], wBB[16];
#pragma unroll
  for (int c = 0; c < 16; c++){
    wAA[c] = s_w[c*16 + kyA*4 + kxA];
    wAB[c] = s_w[c*16 + kyA*4 + kxB];
    wBA[c] = s_w[c*16 + kyB*4 + kxA];
    wBB[c] = s_w[c*16 + kyB*4 + kxB];
  }
  const int lx = ((tx + 1) >> 1) + 1;
  const int ly0 = ((ty + 1) >> 1) + 1;
  const float* xb = x + (size_t)bz*65536;
  float* ob = out + (size_t)bz*65536;
  float lsum = 0.f;
#pragma unroll
  for (int k = 0; k < 4; k++){
    int ly = ly0 + 4*k;
    float acc = bd;
#pragma unroll
    for (int c = 0; c < 16; c++){
      const float* sp = s_t3 + c*324;
      acc = fmaf(sp[(ly-1)*18 + lx-1], wAA[c], acc);
      acc = fmaf(sp[(ly-1)*18 + lx],   wAB[c], acc);
      acc = fmaf(sp[ly*18 + lx-1],     wBA[c], acc);
      acc = fmaf(sp[ly*18 + lx],       wBB[c], acc);
    }
    float o = tanhf(acc);
    int off = (oy0 + ty + 8*k)*256 + ox0 + tx;
    ob[off] = o;
    float d = xb[off] - o;
    lsum = fmaf(d, d, lsum);
  }
  int lane = tid & 31, warp = tid >> 5;
  float r = warp_sum(lsum);
  if (lane == 0) s_red[warp] = r;
  __syncthreads();
  const int blk = (bz*8 + blockIdx.y)*8 + blockIdx.x;
  if (tid == 0){
    float t = 0.f;
#pragma unroll
    for (int w = 0; w < 8; w++) t += s_red[w];
    g_partH[blk] = t;
  }
  __syncthreads();
  if (tid == 0){
    __threadfence();
    s_last = (atomicAdd(&g_c4, 1u) == 4095u);
  }
  __syncthreads();
  if (s_last){
    __threadfence();
    __shared__ double s_dred[8];
    double e = 0.0, h = 0.0;
    for (int i = tid; i < 1024; i += 256) e += (double)g_partE[i];
    for (int i = tid; i < 4096; i += 256) h += (double)g_partH[i];
    double t = e*1.2/524288.0 + h/4194304.0;  // (codebook + 0.2*commit) + recon
#pragma unroll
    for (int o = 16; o > 0; o >>= 1) t += __shfl_down_sync(0xffffffffu, t, o);
    if (lane == 0) s_dred[warp] = t;
    __syncthreads();
    if (tid == 0){
      double sum = 0.0;
      for (int w = 0; w < 8; w++) sum += s_dred[w];
      out_loss[0] = (float)sum;
      g_c4 = 0;
    }
  }
}

// ---------------- launch ----------------
extern "C" void kernel_launch(void* const* d_in, const int* in_sizes, int n_in,
                              void* d_out, int out_size){
  const float* x    = (const float*)d_in[0];
  const float* w1   = (const float*)d_in[1];
  const float* b1   = (const float*)d_in[2];
  const float* g1   = (const float*)d_in[3];
  const float* be1  = (const float*)d_in[4];
  const float* w2   = (const float*)d_in[5];
  const float* b2   = (const float*)d_in[6];
  const float* g2   = (const float*)d_in[7];
  const float* be2  = (const float*)d_in[8];
  const float* wpre = (const float*)d_in[9];
  const float* bpre = (const float*)d_in[10];
  const float* emb  = (const float*)d_in[11];
  const float* wpost= (const float*)d_in[12];
  const float* bpost= (const float*)d_in[13];
  const float* wd1  = (const float*)d_in[14];
  const float* bd1  = (const float*)d_in[15];
  const float* g3   = (const float*)d_in[16];
  const float* be3  = (const float*)d_in[17];
  const float* wd2  = (const float*)d_in[18];
  const float* bd2  = (const float*)d_in[19];
  float* out = (float*)d_out;

  const int smem2 = 4*4488*(int)sizeof(float);   // 71.8 KB
  static int s_attr_done = 0;
  if (!s_attr_done){
    cudaFuncSetAttribute(k_conv2, cudaFuncAttributeMaxDynamicSharedMemorySize, smem2);
    s_attr_done = 1;
  }

  k_conv1 <<<dim3(4,4,64), dim3(32,8)>>>(x, w1, b1, g1, be1);
  k_conv2 <<<dim3(2,2,64), dim3(32,8), smem2>>>(w2, b2, g2, be2);
  k_vq    <<<1024,256>>>(wpre, bpre, emb, wpost, bpost);
  k_convt1<<<dim3(4,4,64), dim3(32,16)>>>(wd1, bd1, g3, be3);
  k_convt2<<<dim3(8,8,64), dim3(32,8)>>>(x, wd2, bd2, out, out + (out_size - 1));
}

// round 9
// speedup vs baseline: 1.0005x; 1.0005x over previous
#include <cuda_runtime.h>
#include <math.h>

// ---------------- scratch (device globals; no allocation) ----------------
__device__ float g_t1[64*16*128*128];   // conv1 raw out
__device__ float g_t3[64*16*128*128];   // convT1 raw out
__device__ float g_t2[64*4*64*64];      // conv2 out
__device__ float g_di[64*4*64*64];      // post-VQ 1x1 out
__device__ float g_partA[1024*32];
__device__ float g_partF[1024*32];
__device__ float g_partC[256*8];
__device__ float g_partE[1024];
__device__ float g_partH[4096];
__device__ float g_bn1[32];  // scale[16], shift[16]
__device__ float g_bn2[8];
__device__ float g_bn3[32];
__device__ unsigned int g_c1, g_c2, g_c3, g_c4;   // zero-init; reset by last block

__device__ __forceinline__ float warp_sum(float v){
#pragma unroll
  for (int o = 16; o > 0; o >>= 1) v += __shfl_down_sync(0xffffffffu, v, o);
  return v;
}

// Deterministic finalize of [nblk][32] partials (16 channels) into bn[32].
// Runs in ONE block of 256 threads; fixed assignment + fixed tree order.
__device__ void bn_finalize32(const float* part, int nblk, float* bn,
                              const float* g, const float* be, double invN,
                              int tid){
  __shared__ double ssf[16], qqf[16];
  int c = tid >> 4;           // 16 threads per channel
  int sub = tid & 15;
  double s = 0.0, q = 0.0;
  for (int i = sub; i < nblk; i += 16){
    s += (double)part[i*32 + c];
    q += (double)part[i*32 + 16 + c];
  }
  // reduce 16 lanes within half-warp (lanes of same channel are contiguous)
#pragma unroll
  for (int o = 8; o > 0; o >>= 1){
    s += __shfl_down_sync(0xffffffffu, s, o, 16);
    q += __shfl_down_sync(0xffffffffu, q, o, 16);
  }
  if (sub == 0){ ssf[c] = s; qqf[c] = q; }
  __syncthreads();
  if (tid < 16){
    double S = ssf[tid], Q = qqf[tid];
    double mean = S*invN;
    double var  = Q*invN - mean*mean;
    float scale = (float)((double)g[tid] / sqrt(var + 1e-5));
    bn[tid] = scale;
    bn[16 + tid] = be[tid] - (float)mean * scale;
  }
}

// ---------------- K1: conv1 (1->16, k4 s2 p1) + store t1 + BN1 partials + BN1 finalize ----------------
// grid (4,4,64), block (32,8). warp = oc pair, lane = column, walk 32 rows.
__global__ void k_conv1(const float* __restrict__ x, const float* __restrict__ w1,
                        const float* __restrict__ b1,
                        const float* __restrict__ g1, const float* __restrict__ be1){
  __shared__ float s_in[66*68];
  __shared__ int s_last;
  const int bz = blockIdx.z;
  const int ox0 = blockIdx.x*32, oy0 = blockIdx.y*32;
  const int w = threadIdx.y, tx = threadIdx.x;
  const int tid = w*32 + tx;
  const int oc0 = 2*w, oc1 = 2*w + 1;
  float wr0[16], wr1[16];
#pragma unroll
  for (int j = 0; j < 16; j++){ wr0[j] = w1[oc0*16 + j]; wr1[j] = w1[oc1*16 + j]; }
  const float bb0 = b1[oc0], bb1 = b1[oc1];
  const float* xb = x + (size_t)bz*65536;
  for (int j = tid; j < 66*66; j += 256){
    int r = j/66, c = j - r*66;
    int gr = oy0*2 - 1 + r, gc = ox0*2 - 1 + c;
    float v = 0.f;
    if ((unsigned)gr < 256u && (unsigned)gc < 256u) v = xb[gr*256 + gc];
    s_in[r*68 + c] = v;
  }
  __syncthreads();
  float s0 = 0.f, q0 = 0.f, s1 = 0.f, q1 = 0.f;
  float* o0 = g_t1 + (size_t)bz*262144 + (size_t)oc0*16384 + (oy0)*128 + ox0 + tx;
  float* o1 = o0 + 16384;
  float r0[4], r1[4];
  {
    float2 u0 = *(const float2*)&s_in[0*68 + 2*tx];
    float2 u1 = *(const float2*)&s_in[0*68 + 2*tx + 2];
    float2 v0 = *(const float2*)&s_in[1*68 + 2*tx];
    float2 v1 = *(const float2*)&s_in[1*68 + 2*tx + 2];
    r0[0]=u0.x; r0[1]=u0.y; r0[2]=u1.x; r0[3]=u1.y;
    r1[0]=v0.x; r1[1]=v0.y; r1[2]=v1.x; r1[3]=v1.y;
  }
#pragma unroll 4
  for (int y = 0; y < 32; y++){
    float r2[4], r3[4];
    {
      float2 u0 = *(const float2*)&s_in[(2*y+2)*68 + 2*tx];
      float2 u1 = *(const float2*)&s_in[(2*y+2)*68 + 2*tx + 2];
      float2 v0 = *(const float2*)&s_in[(2*y+3)*68 + 2*tx];
      float2 v1 = *(const float2*)&s_in[(2*y+3)*68 + 2*tx + 2];
      r2[0]=u0.x; r2[1]=u0.y; r2[2]=u1.x; r2[3]=u1.y;
      r3[0]=v0.x; r3[1]=v0.y; r3[2]=v1.x; r3[3]=v1.y;
    }
    float a0 = bb0, a1 = bb1;
#pragma unroll
    for (int j = 0; j < 4; j++){
      a0 = fmaf(r0[j], wr0[j],    a0);  a1 = fmaf(r0[j], wr1[j],    a1);
      a0 = fmaf(r1[j], wr0[4+j],  a0);  a1 = fmaf(r1[j], wr1[4+j],  a1);
      a0 = fmaf(r2[j], wr0[8+j],  a0);  a1 = fmaf(r2[j], wr1[8+j],  a1);
      a0 = fmaf(r3[j], wr0[12+j], a0);  a1 = fmaf(r3[j], wr1[12+j], a1);
    }
    o0[y*128] = a0;  o1[y*128] = a1;
    s0 += a0; q0 = fmaf(a0, a0, q0);
    s1 += a1; q1 = fmaf(a1, a1, q1);
#pragma unroll
    for (int j = 0; j < 4; j++){ r0[j] = r2[j]; r1[j] = r3[j]; }
  }
  s0 = warp_sum(s0); q0 = warp_sum(q0);
  s1 = warp_sum(s1); q1 = warp_sum(q1);
  const int blk = (bz*4 + blockIdx.y)*4 + blockIdx.x;
  if (tx == 0){
    g_partA[blk*32 + oc0] = s0;
    g_partA[blk*32 + oc1] = s1;
    g_partA[blk*32 + 16 + oc0] = q0;
    g_partA[blk*32 + 16 + oc1] = q1;
  }
  __syncthreads();
  if (tid == 0){
    __threadfence();
    s_last = (atomicAdd(&g_c1, 1u) == 1023u);
  }
  __syncthreads();
  if (s_last){
    __threadfence();
    bn_finalize32(g_partA, 1024, g_bn1, g1, be1, 1.0/1048576.0, tid);
    if (tid == 0) g_c1 = 0;
  }
}

// ---------------- K2: BN1+ReLU + conv2 (16->4, k4 s2 p1) + BN2 partials + BN2 finalize ----------------
// grid (2,2,64), block (32,8). 32x32 t2 tile, 4-channel staged input (dynamic smem 71.8 KB).
__global__ void k_conv2(const float* __restrict__ w2, const float* __restrict__ b2,
                        const float* __restrict__ g2, const float* __restrict__ be2){
  extern __shared__ float s_in[];     // 4 * 66*68 floats
  __shared__ float s_w2[1024];
  __shared__ float s_bn[32];
  __shared__ float s_red[8*8];
  __shared__ int s_last;
  const int bz = blockIdx.z;
  const int ox0 = blockIdx.x*32, oy0 = blockIdx.y*32;
  const int ty = threadIdx.y, tx = threadIdx.x;
  const int tid = ty*32 + tx;
  for (int j = tid; j < 1024; j += 256) s_w2[j] = w2[j];
  if (tid < 32) s_bn[tid] = g_bn1[tid];
  float acc[4][4];
#pragma unroll
  for (int o = 0; o < 4; o++){
    float bo = b2[o];
#pragma unroll
    for (int k = 0; k < 4; k++) acc[o][k] = bo;
  }
  const float* t1b = g_t1 + (size_t)bz*262144;
  for (int st = 0; st < 4; st++){
    __syncthreads();
#pragma unroll
    for (int c4 = 0; c4 < 4; c4++){
      int c = st*4 + c4;
      float sc = s_bn[c], sh = s_bn[16+c];
      const float* inp = t1b + c*16384;
      for (int j = tid; j < 66*66; j += 256){
        int r = j/66, cc = j - r*66;
        int gr = 2*oy0 - 1 + r, gc = 2*ox0 - 1 + cc;
        float v = 0.f;
        if ((unsigned)gr < 128u && (unsigned)gc < 128u)
          v = fmaxf(fmaf(inp[gr*128 + gc], sc, sh), 0.f);
        s_in[c4*4488 + r*68 + cc] = v;
      }
    }
    __syncthreads();
#pragma unroll
    for (int c4 = 0; c4 < 4; c4++){
      int c = st*4 + c4;
      const float* sp = s_in + c4*4488;
#pragma unroll
      for (int ky = 0; ky < 4; ky++){
        float wk[4][4];
#pragma unroll
        for (int o = 0; o < 4; o++)
#pragma unroll
          for (int kx = 0; kx < 4; kx++)
            wk[o][kx] = s_w2[((o*16 + c)*4 + ky)*4 + kx];
#pragma unroll
        for (int k = 0; k < 4; k++){
          int rb = (2*(ty + 8*k) + ky)*68 + 2*tx;
          float2 va = *(const float2*)&sp[rb];
          float2 vb = *(const float2*)&sp[rb + 2];
#pragma unroll
          for (int o = 0; o < 4; o++){
            acc[o][k] = fmaf(va.x, wk[o][0], acc[o][k]);
            acc[o][k] = fmaf(va.y, wk[o][1], acc[o][k]);
            acc[o][k] = fmaf(vb.x, wk[o][2], acc[o][k]);
            acc[o][k] = fmaf(vb.y, wk[o][3], acc[o][k]);
          }
        }
      }
    }
  }
  float st8[8];
#pragma unroll
  for (int v = 0; v < 8; v++) st8[v] = 0.f;
  float* outb = g_t2 + bz*16384;
#pragma unroll
  for (int k = 0; k < 4; k++){
    int off = (oy0 + ty + 8*k)*64 + ox0 + tx;
#pragma unroll
    for (int o = 0; o < 4; o++){
      float a = acc[o][k];
      outb[o*4096 + off] = a;
      st8[o] += a;
      st8[4+o] = fmaf(a, a, st8[4+o]);
    }
  }
  int lane = tid & 31, warp = tid >> 5;
#pragma unroll
  for (int v = 0; v < 8; v++){
    float r = warp_sum(st8[v]);
    if (lane == 0) s_red[warp*8 + v] = r;
  }
  __syncthreads();
  const int blk = (bz*2 + blockIdx.y)*2 + blockIdx.x;
  if (tid < 8){
    float t = 0.f;
#pragma unroll
    for (int w = 0; w < 8; w++) t += s_red[w*8 + tid];
    g_partC[blk*8 + tid] = t;
  }
  __syncthreads();
  if (tid == 0){
    __threadfence();
    s_last = (atomicAdd(&g_c2, 1u) == 255u);
  }
  __syncthreads();
  if (s_last){
    __threadfence();
    // BN2 finalize: partC [256][8], 4 channels
    __shared__ double ss[8], qq[8];
    for (int c = 0; c < 4; c++){
      double s = (double)g_partC[tid*8 + c];
      double q = (double)g_partC[tid*8 + 4 + c];
#pragma unroll
      for (int o = 16; o > 0; o >>= 1){
        s += __shfl_down_sync(0xffffffffu, s, o);
        q += __shfl_down_sync(0xffffffffu, q, o);
      }
      if (lane == 0){ ss[warp] = s; qq[warp] = q; }
      __syncthreads();
      if (tid == 0){
        double S = 0.0, Q = 0.0;
#pragma unroll
        for (int w = 0; w < 8; w++){ S += ss[w]; Q += qq[w]; }
        const double invN = 1.0/262144.0;
        double mean = S*invN;
        double var  = Q*invN - mean*mean;
        float scale = (float)((double)g2[c] / sqrt(var + 1e-5));
        g_bn2[c] = scale;
        g_bn2[4 + c] = be2[c] - (float)mean * scale;
      }
      __syncthreads();
    }
    if (tid == 0) g_c2 = 0;
  }
}

// ---------------- K3: BN2+ReLU + pre1x1 + VQ + loss + post1x1 ----------------
__global__ void k_vq(const float* __restrict__ wpre, const float* __restrict__ bpre,
                     const float* __restrict__ emb,
                     const float* __restrict__ wpost, const float* __restrict__ bpost){
  __shared__ float s_e[128];
  __shared__ float s_ee[64];
  __shared__ float s_red[8];
  int tid = threadIdx.x;
  if (tid < 128) s_e[tid] = emb[tid];
  __syncthreads();
  if (tid < 64) s_ee[tid] = s_e[2*tid]*s_e[2*tid] + s_e[2*tid+1]*s_e[2*tid+1];
  __syncthreads();
  int i = blockIdx.x*256 + tid;
  int b = i >> 12, p = i & 4095;
  const float* tb = g_t2 + b*16384 + p;
  float h0 = fmaxf(fmaf(tb[0],     g_bn2[0], g_bn2[4]), 0.f);
  float h1 = fmaxf(fmaf(tb[4096],  g_bn2[1], g_bn2[5]), 0.f);
  float h2 = fmaxf(fmaf(tb[8192],  g_bn2[2], g_bn2[6]), 0.f);
  float h3 = fmaxf(fmaf(tb[12288], g_bn2[3], g_bn2[7]), 0.f);
  float z0 = bpre[0] + wpre[0]*h0 + wpre[1]*h1 + wpre[2]*h2 + wpre[3]*h3;
  float z1 = bpre[1] + wpre[4]*h0 + wpre[5]*h1 + wpre[6]*h2 + wpre[7]*h3;
  float zz = z0*z0 + z1*z1;
  float best = 3.402823466e38f; int bi = 0;
  for (int k = 0; k < 64; k++){
    float d = zz - 2.f*(z0*s_e[2*k] + z1*s_e[2*k+1]) + s_ee[k];
    if (d < best){ best = d; bi = k; }
  }
  float q0 = s_e[2*bi], q1 = s_e[2*bi+1];
  float l = (q0 - z0)*(q0 - z0) + (q1 - z1)*(q1 - z1);
  float qs0 = z0 + (q0 - z0), qs1 = z1 + (q1 - z1);
  float* db = g_di + b*16384 + p;
#pragma unroll
  for (int o = 0; o < 4; o++)
    db[o*4096] = bpost[o] + wpost[2*o]*qs0 + wpost[2*o+1]*qs1;
  int lane = tid & 31, warp = tid >> 5;
  float r = warp_sum(l);
  if (lane == 0) s_red[warp] = r;
  __syncthreads();
  if (tid == 0){
    float t = 0.f;
#pragma unroll
    for (int w = 0; w < 8; w++) t += s_red[w];
    g_partE[blockIdx.x] = t;
  }
}

// ---------------- K4: convT1 (4->16, k4 s2 p1) + store t3 + BN3 partials + BN3 finalize ----------------
// grid (4,4,64), block (32,16). warp = oc, lane = column, row-pair walk.
__global__ void k_convt1(const float* __restrict__ wd1, const float* __restrict__ bd1,
                         const float* __restrict__ g3, const float* __restrict__ be3){
  __shared__ float s_in[4*324];
  __shared__ int s_last;
  const int bz = blockIdx.z;
  const int ox0 = blockIdx.x*32, oy0 = blockIdx.y*32;
  const int oc = threadIdx.y, tx = threadIdx.x;
  const int tid = oc*32 + tx;
  const int kxA = (tx & 1) ? 2 : 3;
  const int kxB = (tx & 1) ? 0 : 1;
  float wA[4][4], wB[4][4];
#pragma unroll
  for (int c = 0; c < 4; c++)
#pragma unroll
    for (int ky = 0; ky < 4; ky++){
      wA[c][ky] = wd1[c*256 + oc*16 + ky*4 + kxA];
      wB[c][ky] = wd1[c*256 + oc*16 + ky*4 + kxB];
    }
  const float bb = bd1[oc];
  const int iyb = oy0/2 - 1, ixb = ox0/2 - 1;
  const float* inb = g_di + bz*16384;
  for (int j = tid; j < 1296; j += 512){
    int c = j/324, rem = j - c*324, r = rem/18, cc = rem - r*18;
    int iy = iyb + r, ix = ixb + cc;
    float v = 0.f;
    if ((unsigned)iy < 64u && (unsigned)ix < 64u) v = inb[c*4096 + iy*64 + ix];
    s_in[c*324 + rem] = v;
  }
  __syncthreads();
  const int lx = ((tx + 1) >> 1) + 1;
  float s = 0.f, q = 0.f;
  float* ob = g_t3 + (size_t)bz*262144 + (size_t)oc*16384 + oy0*128 + ox0 + tx;
#pragma unroll 2
  for (int a = 0; a <= 16; a++){
    int ly = a + 1;
    float accO = bb, accE = bb;
#pragma unroll
    for (int c = 0; c < 4; c++){
      const float* sp = s_in + c*324;
      float vA0 = sp[(ly-1)*18 + lx-1];
      float vA1 = sp[(ly-1)*18 + lx];
      float vB0 = sp[ly*18 + lx-1];
      float vB1 = sp[ly*18 + lx];
      accO = fmaf(vA0, wA[c][2], accO);
      accO = fmaf(vA1, wB[c][2], accO);
      accO = fmaf(vB0, wA[c][0], accO);
      accO = fmaf(vB1, wB[c][0], accO);
      accE = fmaf(vA0, wA[c][3], accE);
      accE = fmaf(vA1, wB[c][3], accE);
      accE = fmaf(vB0, wA[c][1], accE);
      accE = fmaf(vB1, wB[c][1], accE);
    }
    if (a >= 1){                       // y = 2a-1 (odd)
      ob[(2*a - 1)*128] = accO;
      s += accO; q = fmaf(accO, accO, q);
    }
    if (a <= 15){                      // y = 2a (even)
      ob[(2*a)*128] = accE;
      s += accE; q = fmaf(accE, accE, q);
    }
  }
  s = warp_sum(s); q = warp_sum(q);
  const int blk = (bz*4 + blockIdx.y)*4 + blockIdx.x;
  if (tx == 0){
    g_partF[blk*32 + oc] = s;
    g_partF[blk*32 + 16 + oc] = q;
  }
  __syncthreads();
  if (tid == 0){
    __threadfence();
    s_last = (atomicAdd(&g_c3, 1u) == 1023u);
  }
  __syncthreads();
  if (s_last){
    __threadfence();
    if (tid < 256)
      bn_finalize32(g_partF, 1024, g_bn3, g3, be3, 1.0/1048576.0, tid);
    if (tid == 0) g_c3 = 0;
  }
}

// ---------------- K5: BN3+ReLU + convT2 (16->1) + tanh + recon + total loss ----------------
// grid (8,8,64), block (32,8). Parity-resolved weights in registers.
__global__ void k_convt2(const float* __restrict__ x, const float* __restrict__ wd2,
                         const float* __restrict__ bd2, float* __restrict__ out,
                         float* __restrict__ out_loss){
  __shared__ float s_t3[16*324];
  __shared__ float s_w[256];
  __shared__ float s_bn[32];
  __shared__ float s_red[8];
  __shared__ int s_last;
  const int bz = blockIdx.z;
  const int ox0 = blockIdx.x*32, oy0 = blockIdx.y*32;
  const int ty = threadIdx.y, tx = threadIdx.x;
  const int tid = ty*32 + tx;
  s_w[tid] = wd2[tid];
  if (tid < 32) s_bn[tid] = g_bn3[tid];
  const float bd = bd2[0];
  __syncthreads();
  const int tyb = oy0/2 - 1, txb = ox0/2 - 1;
  const float* inb = g_t3 + (size_t)bz*262144;
  for (int j = tid; j < 16*324; j += 256){
    int c = j/324, rem = j - c*324, r = rem/18, cc = rem - r*18;
    int iy = tyb + r, ix = txb + cc;
    float v = 0.f;
    if ((unsigned)iy < 128u && (unsigned)ix < 128u)
      v = fmaxf(fmaf(inb[c*16384 + iy*128 + ix], s_bn[c], s_bn[16+c]), 0.f);
    s_t3[c*324 + rem] = v;
  }
  __syncthreads();
  const int kyA = (ty & 1) ? 2 : 3, kyB = (ty & 1) ? 0 : 1;
  const int kxA = (tx & 1) ? 2 : 3, kxB = (tx & 1) ? 0 : 1;
  float wAA[16], wAB[16], wBA[16], wBB[16];
#pragma unroll
  for (int c = 0; c < 16; c++){
    wAA[c] = s_w[c*16 + kyA*4 + kxA];
    wAB[c] = s_w[c*16 + kyA*4 + kxB];
    wBA[c] = s_w[c*16 + kyB*4 + kxA];
    wBB[c] = s_w[c*16 + kyB*4 + kxB];
  }
  const int lx = ((tx + 1) >> 1) + 1;
  const int ly0 = ((ty + 1) >> 1) + 1;
  const float* xb = x + (size_t)bz*65536;
  float* ob = out + (size_t)bz*65536;
  float lsum = 0.f;
#pragma unroll
  for (int k = 0; k < 4; k++){
    int ly = ly0 + 4*k;
    float acc = bd;
#pragma unroll
    for (int c = 0; c < 16; c++){
      const float* sp = s_t3 + c*324;
      acc = fmaf(sp[(ly-1)*18 + lx-1], wAA[c], acc);
      acc = fmaf(sp[(ly-1)*18 + lx],   wAB[c], acc);
      acc = fmaf(sp[ly*18 + lx-1],     wBA[c], acc);
      acc = fmaf(sp[ly*18 + lx],       wBB[c], acc);
    }
    float o = tanhf(acc);
    int off = (oy0 + ty + 8*k)*256 + ox0 + tx;
    ob[off] = o;
    float d = xb[off] - o;
    lsum = fmaf(d, d, lsum);
  }
  int lane = tid & 31, warp = tid >> 5;
  float r = warp_sum(lsum);
  if (lane == 0) s_red[warp] = r;
  __syncthreads();
  const int blk = (bz*8 + blockIdx.y)*8 + blockIdx.x;
  if (tid == 0){
    float t = 0.f;
#pragma unroll
    for (int w = 0; w < 8; w++) t += s_red[w];
    g_partH[blk] = t;
  }
  __syncthreads();
  if (tid == 0){
    __threadfence();
    s_last = (atomicAdd(&g_c4, 1u) == 4095u);
  }
  __syncthreads();
  if (s_last){
    __threadfence();
    __shared__ double s_dred[8];
    double e = 0.0, h = 0.0;
    for (int i = tid; i < 1024; i += 256) e += (double)g_partE[i];
    for (int i = tid; i < 4096; i += 256) h += (double)g_partH[i];
    double t = e*1.2/524288.0 + h/4194304.0;  // (codebook + 0.2*commit) + recon
#pragma unroll
    for (int o = 16; o > 0; o >>= 1) t += __shfl_down_sync(0xffffffffu, t, o);
    if (lane == 0) s_dred[warp] = t;
    __syncthreads();
    if (tid == 0){
      double sum = 0.0;
      for (int w = 0; w < 8; w++) sum += s_dred[w];
      out_loss[0] = (float)sum;
      g_c4 = 0;
    }
  }
}

// ---------------- launch ----------------
extern "C" void kernel_launch(void* const* d_in, const int* in_sizes, int n_in,
                              void* d_out, int out_size){
  const float* x    = (const float*)d_in[0];
  const float* w1   = (const float*)d_in[1];
  const float* b1   = (const float*)d_in[2];
  const float* g1   = (const float*)d_in[3];
  const float* be1  = (const float*)d_in[4];
  const float* w2   = (const float*)d_in[5];
  const float* b2   = (const float*)d_in[6];
  const float* g2   = (const float*)d_in[7];
  const float* be2  = (const float*)d_in[8];
  const float* wpre = (const float*)d_in[9];
  const float* bpre = (const float*)d_in[10];
  const float* emb  = (const float*)d_in[11];
  const float* wpost= (const float*)d_in[12];
  const float* bpost= (const float*)d_in[13];
  const float* wd1  = (const float*)d_in[14];
  const float* bd1  = (const float*)d_in[15];
  const float* g3   = (const float*)d_in[16];
  const float* be3  = (const float*)d_in[17];
  const float* wd2  = (const float*)d_in[18];
  const float* bd2  = (const float*)d_in[19];
  float* out = (float*)d_out;

  const int smem2 = 4*4488*(int)sizeof(float);   // 71.8 KB
  static int s_attr_done = 0;
  if (!s_attr_done){
    cudaFuncSetAttribute(k_conv2, cudaFuncAttributeMaxDynamicSharedMemorySize, smem2);
    s_attr_done = 1;
  }

  k_conv1 <<<dim3(4,4,64), dim3(32,8)>>>(x, w1, b1, g1, be1);
  k_conv2 <<<dim3(2,2,64), dim3(32,8), smem2>>>(w2, b2, g2, be2);
  k_vq    <<<1024,256>>>(wpre, bpre, emb, wpost, bpost);
  k_convt1<<<dim3(4,4,64), dim3(32,16)>>>(wd1, bd1, g3, be3);
  k_convt2<<<dim3(8,8,64), dim3(32,8)>>>(x, wd2, bd2, out, out + (out_size - 1));
}

// round 10
// speedup vs baseline: 1.3139x; 1.3132x over previous
#include <cuda_runtime.h>
#include <math.h>

// ---------------- scratch (device globals; no allocation) ----------------
__device__ float g_t1[64*16*128*128];   // conv1 raw out
__device__ float g_t3[64*16*128*128];   // convT1 raw out
__device__ float g_t2[64*4*64*64];      // conv2 out
__device__ float g_di[64*4*64*64];      // post-VQ 1x1 out
__device__ float g_partA[1024*32];
__device__ float g_partF[1024*32];
__device__ float g_partC[256*8];
__device__ float g_partE[1024];
__device__ float g_partH[4096];
__device__ float g_bn3[32];

__device__ __forceinline__ float warp_sum(float v){
#pragma unroll
  for (int o = 16; o > 0; o >>= 1) v += __shfl_down_sync(0xffffffffu, v, o);
  return v;
}

// ---------------- K1: conv1 (1->16, k4 s2 p1) + store t1 + BN1 partials ----------------
// grid (4,4,64), block (32,8). warp = oc pair, lane = column, walk 32 rows.
__global__ void k_conv1(const float* __restrict__ x, const float* __restrict__ w1,
                        const float* __restrict__ b1){
  __shared__ float s_in[66*68];
  const int bz = blockIdx.z;
  const int ox0 = blockIdx.x*32, oy0 = blockIdx.y*32;
  const int w = threadIdx.y, tx = threadIdx.x;
  const int tid = w*32 + tx;
  const int oc0 = 2*w, oc1 = 2*w + 1;
  float wr0[16], wr1[16];
#pragma unroll
  for (int j = 0; j < 16; j++){ wr0[j] = w1[oc0*16 + j]; wr1[j] = w1[oc1*16 + j]; }
  const float bb0 = b1[oc0], bb1 = b1[oc1];
  const float* xb = x + (size_t)bz*65536;
  for (int j = tid; j < 66*66; j += 256){
    int r = j/66, c = j - r*66;
    int gr = oy0*2 - 1 + r, gc = ox0*2 - 1 + c;
    float v = 0.f;
    if ((unsigned)gr < 256u && (unsigned)gc < 256u) v = xb[gr*256 + gc];
    s_in[r*68 + c] = v;
  }
  __syncthreads();
  float s0 = 0.f, q0 = 0.f, s1 = 0.f, q1 = 0.f;
  float* o0 = g_t1 + (size_t)bz*262144 + (size_t)oc0*16384 + (oy0)*128 + ox0 + tx;
  float* o1 = o0 + 16384;
  float r0[4], r1[4];
  {
    float2 u0 = *(const float2*)&s_in[0*68 + 2*tx];
    float2 u1 = *(const float2*)&s_in[0*68 + 2*tx + 2];
    float2 v0 = *(const float2*)&s_in[1*68 + 2*tx];
    float2 v1 = *(const float2*)&s_in[1*68 + 2*tx + 2];
    r0[0]=u0.x; r0[1]=u0.y; r0[2]=u1.x; r0[3]=u1.y;
    r1[0]=v0.x; r1[1]=v0.y; r1[2]=v1.x; r1[3]=v1.y;
  }
#pragma unroll 4
  for (int y = 0; y < 32; y++){
    float r2[4], r3[4];
    {
      float2 u0 = *(const float2*)&s_in[(2*y+2)*68 + 2*tx];
      float2 u1 = *(const float2*)&s_in[(2*y+2)*68 + 2*tx + 2];
      float2 v0 = *(const float2*)&s_in[(2*y+3)*68 + 2*tx];
      float2 v1 = *(const float2*)&s_in[(2*y+3)*68 + 2*tx + 2];
      r2[0]=u0.x; r2[1]=u0.y; r2[2]=u1.x; r2[3]=u1.y;
      r3[0]=v0.x; r3[1]=v0.y; r3[2]=v1.x; r3[3]=v1.y;
    }
    float a0 = bb0, a1 = bb1;
#pragma unroll
    for (int j = 0; j < 4; j++){
      a0 = fmaf(r0[j], wr0[j],    a0);  a1 = fmaf(r0[j], wr1[j],    a1);
      a0 = fmaf(r1[j], wr0[4+j],  a0);  a1 = fmaf(r1[j], wr1[4+j],  a1);
      a0 = fmaf(r2[j], wr0[8+j],  a0);  a1 = fmaf(r2[j], wr1[8+j],  a1);
      a0 = fmaf(r3[j], wr0[12+j], a0);  a1 = fmaf(r3[j], wr1[12+j], a1);
    }
    o0[y*128] = a0;  o1[y*128] = a1;
    s0 += a0; q0 = fmaf(a0, a0, q0);
    s1 += a1; q1 = fmaf(a1, a1, q1);
#pragma unroll
    for (int j = 0; j < 4; j++){ r0[j] = r2[j]; r1[j] = r3[j]; }
  }
  s0 = warp_sum(s0); q0 = warp_sum(q0);
  s1 = warp_sum(s1); q1 = warp_sum(q1);
  if (tx == 0){
    int blk = (bz*4 + blockIdx.y)*4 + blockIdx.x;
    g_partA[blk*32 + oc0] = s0;
    g_partA[blk*32 + oc1] = s1;
    g_partA[blk*32 + 16 + oc0] = q0;
    g_partA[blk*32 + 16 + oc1] = q1;
  }
}

// ---------------- K2: BN1(head-finalized) + ReLU + conv2 (16->4) + BN2 partials ----------------
// grid (2,2,64), block (32,8). Every block deterministically recomputes BN1 scale/shift
// from g_partA (identical fixed-order double reduction in all blocks; no race, no write).
__global__ void k_conv2(const float* __restrict__ w2, const float* __restrict__ b2,
                        const float* __restrict__ g1, const float* __restrict__ be1){
  __shared__ float s_in[66*68];
  __shared__ float s_w2[1024];
  __shared__ float s_bn[32];
  __shared__ float s_red[8*8];
  __shared__ double ssf[16], qqf[16];
  const int bz = blockIdx.z;
  const int ox0 = blockIdx.x*32, oy0 = blockIdx.y*32;
  const int ty = threadIdx.y, tx = threadIdx.x;
  const int tid = ty*32 + tx;
  for (int j = tid; j < 1024; j += 256) s_w2[j] = w2[j];
  // --- BN1 head finalize: 16 threads per channel, fixed tree ---
  {
    int c = tid >> 4, sub = tid & 15;
    double s = 0.0, q = 0.0;
    for (int i = sub; i < 1024; i += 16){
      s += (double)g_partA[i*32 + c];
      q += (double)g_partA[i*32 + 16 + c];
    }
#pragma unroll
    for (int o = 8; o > 0; o >>= 1){
      s += __shfl_down_sync(0xffffffffu, s, o, 16);
      q += __shfl_down_sync(0xffffffffu, q, o, 16);
    }
    if (sub == 0){ ssf[c] = s; qqf[c] = q; }
    __syncthreads();
    if (tid < 16){
      const double invN = 1.0/1048576.0;
      double mean = ssf[tid]*invN;
      double var  = qqf[tid]*invN - mean*mean;
      float scale = (float)((double)g1[tid] / sqrt(var + 1e-5));
      s_bn[tid] = scale;
      s_bn[16 + tid] = be1[tid] - (float)mean * scale;
    }
  }
  float acc[4][4];
#pragma unroll
  for (int o = 0; o < 4; o++){
    float bo = b2[o];
#pragma unroll
    for (int k = 0; k < 4; k++) acc[o][k] = bo;
  }
  const float* t1b = g_t1 + (size_t)bz*262144;
  for (int c = 0; c < 16; c++){
    __syncthreads();
    float sc = s_bn[c], sh = s_bn[16+c];
    const float* inp = t1b + c*16384;
    for (int j = tid; j < 66*66; j += 256){
      int r = j/66, cc = j - r*66;
      int gr = 2*oy0 - 1 + r, gc = 2*ox0 - 1 + cc;
      float v = 0.f;
      if ((unsigned)gr < 128u && (unsigned)gc < 128u)
        v = fmaxf(fmaf(inp[gr*128 + gc], sc, sh), 0.f);
      s_in[r*68 + cc] = v;
    }
    __syncthreads();
#pragma unroll
    for (int ky = 0; ky < 4; ky++){
      float wk[4][4];
#pragma unroll
      for (int o = 0; o < 4; o++)
#pragma unroll
        for (int kx = 0; kx < 4; kx++)
          wk[o][kx] = s_w2[((o*16 + c)*4 + ky)*4 + kx];
#pragma unroll
      for (int k = 0; k < 4; k++){
        int rb = (2*(ty + 8*k) + ky)*68 + 2*tx;
        float2 va = *(const float2*)&s_in[rb];
        float2 vb = *(const float2*)&s_in[rb + 2];
#pragma unroll
        for (int o = 0; o < 4; o++){
          acc[o][k] = fmaf(va.x, wk[o][0], acc[o][k]);
          acc[o][k] = fmaf(va.y, wk[o][1], acc[o][k]);
          acc[o][k] = fmaf(vb.x, wk[o][2], acc[o][k]);
          acc[o][k] = fmaf(vb.y, wk[o][3], acc[o][k]);
        }
      }
    }
  }
  float st8[8];
#pragma unroll
  for (int v = 0; v < 8; v++) st8[v] = 0.f;
  float* outb = g_t2 + bz*16384;
#pragma unroll
  for (int k = 0; k < 4; k++){
    int off = (oy0 + ty + 8*k)*64 + ox0 + tx;
#pragma unroll
    for (int o = 0; o < 4; o++){
      float a = acc[o][k];
      outb[o*4096 + off] = a;
      st8[o] += a;
      st8[4+o] = fmaf(a, a, st8[4+o]);
    }
  }
  int lane = tid & 31, warp = tid >> 5;
#pragma unroll
  for (int v = 0; v < 8; v++){
    float r = warp_sum(st8[v]);
    if (lane == 0) s_red[warp*8 + v] = r;
  }
  __syncthreads();
  if (tid < 8){
    float t = 0.f;
#pragma unroll
    for (int w = 0; w < 8; w++) t += s_red[w*8 + tid];
    int blk = (bz*2 + blockIdx.y)*2 + blockIdx.x;
    g_partC[blk*8 + tid] = t;
  }
}

// ---------------- K3: BN2(head-finalized) + ReLU + pre1x1 + VQ + loss + post1x1 ----------------
__global__ void k_vq(const float* __restrict__ g2, const float* __restrict__ be2,
                     const float* __restrict__ wpre, const float* __restrict__ bpre,
                     const float* __restrict__ emb,
                     const float* __restrict__ wpost, const float* __restrict__ bpost){
  __shared__ float s_e[128];
  __shared__ float s_ee[64];
  __shared__ float s_red[8];
  __shared__ float s_bn2[8];
  int tid = threadIdx.x;
  if (tid < 128) s_e[tid] = emb[tid];
  // --- BN2 head finalize: warp w (<4) handles channel w, fixed order ---
  int lane = tid & 31, warp = tid >> 5;
  if (warp < 4){
    double s = 0.0, q = 0.0;
    for (int i = lane; i < 256; i += 32){
      s += (double)g_partC[i*8 + warp];
      q += (double)g_partC[i*8 + 4 + warp];
    }
#pragma unroll
    for (int o = 16; o > 0; o >>= 1){
      s += __shfl_down_sync(0xffffffffu, s, o);
      q += __shfl_down_sync(0xffffffffu, q, o);
    }
    if (lane == 0){
      const double invN = 1.0/262144.0;
      double mean = s*invN;
      double var  = q*invN - mean*mean;
      float scale = (float)((double)g2[warp] / sqrt(var + 1e-5));
      s_bn2[warp] = scale;
      s_bn2[4 + warp] = be2[warp] - (float)mean * scale;
    }
  }
  __syncthreads();
  if (tid < 64) s_ee[tid] = s_e[2*tid]*s_e[2*tid] + s_e[2*tid+1]*s_e[2*tid+1];
  __syncthreads();
  int i = blockIdx.x*256 + tid;
  int b = i >> 12, p = i & 4095;
  const float* tb = g_t2 + b*16384 + p;
  float h0 = fmaxf(fmaf(tb[0],     s_bn2[0], s_bn2[4]), 0.f);
  float h1 = fmaxf(fmaf(tb[4096],  s_bn2[1], s_bn2[5]), 0.f);
  float h2 = fmaxf(fmaf(tb[8192],  s_bn2[2], s_bn2[6]), 0.f);
  float h3 = fmaxf(fmaf(tb[12288], s_bn2[3], s_bn2[7]), 0.f);
  float z0 = bpre[0] + wpre[0]*h0 + wpre[1]*h1 + wpre[2]*h2 + wpre[3]*h3;
  float z1 = bpre[1] + wpre[4]*h0 + wpre[5]*h1 + wpre[6]*h2 + wpre[7]*h3;
  float zz = z0*z0 + z1*z1;
  float best = 3.402823466e38f; int bi = 0;
  for (int k = 0; k < 64; k++){
    float d = zz - 2.f*(z0*s_e[2*k] + z1*s_e[2*k+1]) + s_ee[k];
    if (d < best){ best = d; bi = k; }
  }
  float q0 = s_e[2*bi], q1 = s_e[2*bi+1];
  float l = (q0 - z0)*(q0 - z0) + (q1 - z1)*(q1 - z1);
  float qs0 = z0 + (q0 - z0), qs1 = z1 + (q1 - z1);
  float* db = g_di + b*16384 + p;
#pragma unroll
  for (int o = 0; o < 4; o++)
    db[o*4096] = bpost[o] + wpost[2*o]*qs0 + wpost[2*o+1]*qs1;
  float r = warp_sum(l);
  if (lane == 0) s_red[warp] = r;
  __syncthreads();
  if (tid == 0){
    float t = 0.f;
#pragma unroll
    for (int w = 0; w < 8; w++) t += s_red[w];
    g_partE[blockIdx.x] = t;
  }
}

// ---------------- K4: convT1 (4->16, k4 s2 p1) + store t3 + BN3 partials ----------------
// grid (4,4,64), block (32,16). warp = oc, lane = column, rolling-register row walk.
__global__ void k_convt1(const float* __restrict__ wd1, const float* __restrict__ bd1){
  __shared__ float s_in[4*324];
  const int bz = blockIdx.z;
  const int ox0 = blockIdx.x*32, oy0 = blockIdx.y*32;
  const int oc = threadIdx.y, tx = threadIdx.x;
  const int tid = oc*32 + tx;
  const int kxA = (tx & 1) ? 2 : 3;
  const int kxB = (tx & 1) ? 0 : 1;
  float wA[4][4], wB[4][4];
#pragma unroll
  for (int c = 0; c < 4; c++)
#pragma unroll
    for (int ky = 0; ky < 4; ky++){
      wA[c][ky] = wd1[c*256 + oc*16 + ky*4 + kxA];
      wB[c][ky] = wd1[c*256 + oc*16 + ky*4 + kxB];
    }
  const float bb = bd1[oc];
  const int iyb = oy0/2 - 1, ixb = ox0/2 - 1;
  const float* inb = g_di + bz*16384;
  for (int j = tid; j < 1296; j += 512){
    int c = j/324, rem = j - c*324, r = rem/18, cc = rem - r*18;
    int iy = iyb + r, ix = ixb + cc;
    float v = 0.f;
    if ((unsigned)iy < 64u && (unsigned)ix < 64u) v = inb[c*4096 + iy*64 + ix];
    s_in[c*324 + rem] = v;
  }
  __syncthreads();
  const int lx = ((tx + 1) >> 1) + 1;
  float s = 0.f, q = 0.f;
  float* ob = g_t3 + (size_t)bz*262144 + (size_t)oc*16384 + oy0*128 + ox0 + tx;
  // rolling registers: row pair (pA) = previous iteration's row (pB)
  float pA0[4], pA1[4];
#pragma unroll
  for (int c = 0; c < 4; c++){
    pA0[c] = s_in[c*324 + 0*18 + lx-1];
    pA1[c] = s_in[c*324 + 0*18 + lx];
  }
  for (int a = 0; a <= 16; a++){
    int ly = a + 1;
    float pB0[4], pB1[4];
#pragma unroll
    for (int c = 0; c < 4; c++){
      pB0[c] = s_in[c*324 + ly*18 + lx-1];
      pB1[c] = s_in[c*324 + ly*18 + lx];
    }
    float accO = bb, accE = bb;
#pragma unroll
    for (int c = 0; c < 4; c++){
      accO = fmaf(pA0[c], wA[c][2], accO);
      accO = fmaf(pA1[c], wB[c][2], accO);
      accO = fmaf(pB0[c], wA[c][0], accO);
      accO = fmaf(pB1[c], wB[c][0], accO);
      accE = fmaf(pA0[c], wA[c][3], accE);
      accE = fmaf(pA1[c], wB[c][3], accE);
      accE = fmaf(pB0[c], wA[c][1], accE);
      accE = fmaf(pB1[c], wB[c][1], accE);
    }
    if (a >= 1){                       // y = 2a-1 (odd)
      ob[(2*a - 1)*128] = accO;
      s += accO; q = fmaf(accO, accO, q);
    }
    if (a <= 15){                      // y = 2a (even)
      ob[(2*a)*128] = accE;
      s += accE; q = fmaf(accE, accE, q);
    }
#pragma unroll
    for (int c = 0; c < 4; c++){ pA0[c] = pB0[c]; pA1[c] = pB1[c]; }
  }
  s = warp_sum(s); q = warp_sum(q);
  if (tx == 0){
    int blk = (bz*4 + blockIdx.y)*4 + blockIdx.x;
    g_partF[blk*32 + oc] = s;
    g_partF[blk*32 + 16 + oc] = q;
  }
}

// ---------------- K5: BN3 finalize (16 blocks x 256 threads) ----------------
__global__ void k_bnfinF(const float* __restrict__ g, const float* __restrict__ be){
  const int c = blockIdx.x;
  const int tid = threadIdx.x;
  double s = 0.0, q = 0.0;
  for (int i = tid; i < 1024; i += 256){
    s += (double)g_partF[i*32 + c];
    q += (double)g_partF[i*32 + 16 + c];
  }
#pragma unroll
  for (int o = 16; o > 0; o >>= 1){
    s += __shfl_down_sync(0xffffffffu, s, o);
    q += __shfl_down_sync(0xffffffffu, q, o);
  }
  __shared__ double ss[8], qq[8];
  int lane = tid & 31, warp = tid >> 5;
  if (lane == 0){ ss[warp] = s; qq[warp] = q; }
  __syncthreads();
  if (tid == 0){
    double S = 0.0, Q = 0.0;
#pragma unroll
    for (int w = 0; w < 8; w++){ S += ss[w]; Q += qq[w]; }
    const double invN = 1.0/1048576.0;
    double mean = S*invN;
    double var  = Q*invN - mean*mean;
    float scale = (float)((double)g[c] / sqrt(var + 1e-5));
    g_bn3[c] = scale;
    g_bn3[16 + c] = be[c] - (float)mean * scale;
  }
}

// ---------------- K6: BN3+ReLU + convT2 (16->1) + tanh + recon partials ----------------
// grid (8,8,64), block (32,8). Parity-resolved weights in registers.
__global__ void k_convt2(const float* __restrict__ x, const float* __restrict__ wd2,
                         const float* __restrict__ bd2, float* __restrict__ out){
  __shared__ float s_t3[16*324];
  __shared__ float s_w[256];
  __shared__ float s_bn[32];
  __shared__ float s_red[8];
  const int bz = blockIdx.z;
  const int ox0 = blockIdx.x*32, oy0 = blockIdx.y*32;
  const int ty = threadIdx.y, tx = threadIdx.x;
  const int tid = ty*32 + tx;
  s_w[tid] = wd2[tid];
  if (tid < 32) s_bn[tid] = g_bn3[tid];
  const float bd = bd2[0];
  __syncthreads();
  const int tyb = oy0/2 - 1, txb = ox0/2 - 1;
  const float* inb = g_t3 + (size_t)bz*262144;
  for (int j = tid; j < 16*324; j += 256){
    int c = j/324, rem = j - c*324, r = rem/18, cc = rem - r*18;
    int iy = tyb + r, ix = txb + cc;
    float v = 0.f;
    if ((unsigned)iy < 128u && (unsigned)ix < 128u)
      v = fmaxf(fmaf(inb[c*16384 + iy*128 + ix], s_bn[c], s_bn[16+c]), 0.f);
    s_t3[c*324 + rem] = v;
  }
  __syncthreads();
  const int kyA = (ty & 1) ? 2 : 3, kyB = (ty & 1) ? 0 : 1;
  const int kxA = (tx & 1) ? 2 : 3, kxB = (tx & 1) ? 0 : 1;
  float wAA[16], wAB[16], wBA[16], wBB[16];
#pragma unroll
  for (int c = 0; c < 16; c++){
    wAA[c] = s_w[c*16 + kyA*4 + kxA];
    wAB[c] = s_w[c*16 + kyA*4 + kxB];
    wBA[c] = s_w[c*16 + kyB*4 + kxA];
    wBB[c] = s_w[c*16 + kyB*4 + kxB];
  }
  const int lx = ((tx + 1) >> 1) + 1;
  const int ly0 = ((ty + 1) >> 1) + 1;
  const float* xb = x + (size_t)bz*65536;
  float* ob = out + (size_t)bz*65536;
  float lsum = 0.f;
#pragma unroll
  for (int k = 0; k < 4; k++){
    int ly = ly0 + 4*k;
    float acc = bd;
#pragma unroll
    for (int c = 0; c < 16; c++){
      const float* sp = s_t3 + c*324;
      acc = fmaf(sp[(ly-1)*18 + lx-1], wAA[c], acc);
      acc = fmaf(sp[(ly-1)*18 + lx],   wAB[c], acc);
      acc = fmaf(sp[ly*18 + lx-1],     wBA[c], acc);
      acc = fmaf(sp[ly*18 + lx],       wBB[c], acc);
    }
    float o = tanhf(acc);
    int off = (oy0 + ty + 8*k)*256 + ox0 + tx;
    ob[off] = o;
    float d = xb[off] - o;
    lsum = fmaf(d, d, lsum);
  }
  int lane = tid & 31, warp = tid >> 5;
  float r = warp_sum(lsum);
  if (lane == 0) s_red[warp] = r;
  __syncthreads();
  if (tid == 0){
    float t = 0.f;
#pragma unroll
    for (int w = 0; w < 8; w++) t += s_red[w];
    int blk = (bz*8 + blockIdx.y)*8 + blockIdx.x;
    g_partH[blk] = t;
  }
}

// ---------------- K7: final loss scalar ----------------
__global__ void k_loss(float* __restrict__ out_loss){
  __shared__ double s_red[8];
  int tid = threadIdx.x;
  double e = 0.0, h = 0.0;
  for (int i = tid; i < 1024; i += 256) e += (double)g_partE[i];
  for (int i = tid; i < 4096; i += 256) h += (double)g_partH[i];
  double t = e*1.2/524288.0 + h/4194304.0;  // (codebook + 0.2*commit) + recon
  int lane = tid & 31, warp = tid >> 5;
#pragma unroll
  for (int o = 16; o > 0; o >>= 1) t += __shfl_down_sync(0xffffffffu, t, o);
  if (lane == 0) s_red[warp] = t;
  __syncthreads();
  if (tid == 0){
    double s = 0.0;
    for (int w = 0; w < 8; w++) s += s_red[w];
    out_loss[0] = (float)s;
  }
}

// ---------------- launch ----------------
extern "C" void kernel_launch(void* const* d_in, const int* in_sizes, int n_in,
                              void* d_out, int out_size){
  const float* x    = (const float*)d_in[0];
  const float* w1   = (const float*)d_in[1];
  const float* b1   = (const float*)d_in[2];
  const float* g1   = (const float*)d_in[3];
  const float* be1  = (const float*)d_in[4];
  const float* w2   = (const float*)d_in[5];
  const float* b2   = (const float*)d_in[6];
  const float* g2   = (const float*)d_in[7];
  const float* be2  = (const float*)d_in[8];
  const float* wpre = (const float*)d_in[9];
  const float* bpre = (const float*)d_in[10];
  const float* emb  = (const float*)d_in[11];
  const float* wpost= (const float*)d_in[12];
  const float* bpost= (const float*)d_in[13];
  const float* wd1  = (const float*)d_in[14];
  const float* bd1  = (const float*)d_in[15];
  const float* g3   = (const float*)d_in[16];
  const float* be3  = (const float*)d_in[17];
  const float* wd2  = (const float*)d_in[18];
  const float* bd2  = (const float*)d_in[19];
  float* out = (float*)d_out;

  k_conv1 <<<dim3(4,4,64), dim3(32,8)>>>(x, w1, b1);
  k_conv2 <<<dim3(2,2,64), dim3(32,8)>>>(w2, b2, g1, be1);
  k_vq    <<<1024,256>>>(g2, be2, wpre, bpre, emb, wpost, bpost);
  k_convt1<<<dim3(4,4,64), dim3(32,16)>>>(wd1, bd1);
  k_bnfinF<<<16,256>>>(g3, be3);
  k_convt2<<<dim3(8,8,64), dim3(32,8)>>>(x, wd2, bd2, out);
  k_loss  <<<1,256>>>(out + (out_size - 1));
}

// round 11
// speedup vs baseline: 1.4220x; 1.0823x over previous
#include <cuda_runtime.h>
#include <math.h>

// ---------------- scratch (device globals; no allocation) ----------------
__device__ float g_t1[64*16*128*128];   // conv1 raw out
__device__ float g_t3[64*16*128*128];   // convT1 raw out
__device__ float g_t2[64*4*64*64];      // conv2 out
__device__ float g_di[64*4*64*64];      // post-VQ 1x1 out
__device__ float g_partA[1024*32];
__device__ float g_partF[1024*32];
__device__ float g_partC[256*8];
__device__ float g_partE[1024];
__device__ float g_partH[4096];
__device__ float g_bn1[32];  // scale[16], shift[16]
__device__ float g_bn2[8];
__device__ float g_bn3[32];

__device__ __forceinline__ float warp_sum(float v){
#pragma unroll
  for (int o = 16; o > 0; o >>= 1) v += __shfl_down_sync(0xffffffffu, v, o);
  return v;
}

// ---------------- K1: conv1 (1->16, k4 s2 p1) + store t1 + BN1 partials ----------------
// grid (4,4,64), block (32,8). warp = oc pair, lane = column, walk 32 rows.
__global__ void k_conv1(const float* __restrict__ x, const float* __restrict__ w1,
                        const float* __restrict__ b1){
  __shared__ float s_in[66*68];
  const int bz = blockIdx.z;
  const int ox0 = blockIdx.x*32, oy0 = blockIdx.y*32;
  const int w = threadIdx.y, tx = threadIdx.x;
  const int tid = w*32 + tx;
  const int oc0 = 2*w, oc1 = 2*w + 1;
  float wr0[16], wr1[16];
#pragma unroll
  for (int j = 0; j < 16; j++){ wr0[j] = w1[oc0*16 + j]; wr1[j] = w1[oc1*16 + j]; }
  const float bb0 = b1[oc0], bb1 = b1[oc1];
  const float* xb = x + (size_t)bz*65536;
  for (int j = tid; j < 66*66; j += 256){
    int r = j/66, c = j - r*66;
    int gr = oy0*2 - 1 + r, gc = ox0*2 - 1 + c;
    float v = 0.f;
    if ((unsigned)gr < 256u && (unsigned)gc < 256u) v = xb[gr*256 + gc];
    s_in[r*68 + c] = v;
  }
  __syncthreads();
  float s0 = 0.f, q0 = 0.f, s1 = 0.f, q1 = 0.f;
  float* o0 = g_t1 + (size_t)bz*262144 + (size_t)oc0*16384 + (oy0)*128 + ox0 + tx;
  float* o1 = o0 + 16384;
  float r0[4], r1[4];
  {
    float2 u0 = *(const float2*)&s_in[0*68 + 2*tx];
    float2 u1 = *(const float2*)&s_in[0*68 + 2*tx + 2];
    float2 v0 = *(const float2*)&s_in[1*68 + 2*tx];
    float2 v1 = *(const float2*)&s_in[1*68 + 2*tx + 2];
    r0[0]=u0.x; r0[1]=u0.y; r0[2]=u1.x; r0[3]=u1.y;
    r1[0]=v0.x; r1[1]=v0.y; r1[2]=v1.x; r1[3]=v1.y;
  }
#pragma unroll 4
  for (int y = 0; y < 32; y++){
    float r2[4], r3[4];
    {
      float2 u0 = *(const float2*)&s_in[(2*y+2)*68 + 2*tx];
      float2 u1 = *(const float2*)&s_in[(2*y+2)*68 + 2*tx + 2];
      float2 v0 = *(const float2*)&s_in[(2*y+3)*68 + 2*tx];
      float2 v1 = *(const float2*)&s_in[(2*y+3)*68 + 2*tx + 2];
      r2[0]=u0.x; r2[1]=u0.y; r2[2]=u1.x; r2[3]=u1.y;
      r3[0]=v0.x; r3[1]=v0.y; r3[2]=v1.x; r3[3]=v1.y;
    }
    float a0 = bb0, a1 = bb1;
#pragma unroll
    for (int j = 0; j < 4; j++){
      a0 = fmaf(r0[j], wr0[j],    a0);  a1 = fmaf(r0[j], wr1[j],    a1);
      a0 = fmaf(r1[j], wr0[4+j],  a0);  a1 = fmaf(r1[j], wr1[4+j],  a1);
      a0 = fmaf(r2[j], wr0[8+j],  a0);  a1 = fmaf(r2[j], wr1[8+j],  a1);
      a0 = fmaf(r3[j], wr0[12+j], a0);  a1 = fmaf(r3[j], wr1[12+j], a1);
    }
    o0[y*128] = a0;  o1[y*128] = a1;
    s0 += a0; q0 = fmaf(a0, a0, q0);
    s1 += a1; q1 = fmaf(a1, a1, q1);
#pragma unroll
    for (int j = 0; j < 4; j++){ r0[j] = r2[j]; r1[j] = r3[j]; }
  }
  s0 = warp_sum(s0); q0 = warp_sum(q0);
  s1 = warp_sum(s1); q1 = warp_sum(q1);
  if (tx == 0){
    int blk = (bz*4 + blockIdx.y)*4 + blockIdx.x;
    g_partA[blk*32 + oc0] = s0;
    g_partA[blk*32 + oc1] = s1;
    g_partA[blk*32 + 16 + oc0] = q0;
    g_partA[blk*32 + 16 + oc1] = q1;
  }
}

// ---------------- BN finalize for [1024][32] partials (BN1 / BN3) ----------------
__global__ void k_bnfin32(int which, const float* __restrict__ g, const float* __restrict__ be){
  const float* part = which ? g_partF : g_partA;
  float* bn = which ? g_bn3 : g_bn1;
  const int c = blockIdx.x;
  const int tid = threadIdx.x;
  double s = 0.0, q = 0.0;
  for (int i = tid; i < 1024; i += 256){
    s += (double)part[i*32 + c];
    q += (double)part[i*32 + 16 + c];
  }
#pragma unroll
  for (int o = 16; o > 0; o >>= 1){
    s += __shfl_down_sync(0xffffffffu, s, o);
    q += __shfl_down_sync(0xffffffffu, q, o);
  }
  __shared__ double ss[8], qq[8];
  int lane = tid & 31, warp = tid >> 5;
  if (lane == 0){ ss[warp] = s; qq[warp] = q; }
  __syncthreads();
  if (tid == 0){
    double S = 0.0, Q = 0.0;
#pragma unroll
    for (int w = 0; w < 8; w++){ S += ss[w]; Q += qq[w]; }
    const double invN = 1.0/1048576.0;
    double mean = S*invN;
    double var  = Q*invN - mean*mean;
    float scale = (float)((double)g[c] / sqrt(var + 1e-5));
    bn[c] = scale;
    bn[16 + c] = be[c] - (float)mean * scale;
  }
}

// ---------------- BN2 finalize: partC [256][8] ----------------
__global__ void k_bnfinC(const float* __restrict__ g, const float* __restrict__ be){
  const int c = blockIdx.x;
  const int tid = threadIdx.x;
  double s = (double)g_partC[tid*8 + c];
  double q = (double)g_partC[tid*8 + 4 + c];
#pragma unroll
  for (int o = 16; o > 0; o >>= 1){
    s += __shfl_down_sync(0xffffffffu, s, o);
    q += __shfl_down_sync(0xffffffffu, q, o);
  }
  __shared__ double ss[8], qq[8];
  int lane = tid & 31, warp = tid >> 5;
  if (lane == 0){ ss[warp] = s; qq[warp] = q; }
  __syncthreads();
  if (tid == 0){
    double S = 0.0, Q = 0.0;
#pragma unroll
    for (int w = 0; w < 8; w++){ S += ss[w]; Q += qq[w]; }
    const double invN = 1.0/262144.0;
    double mean = S*invN;
    double var  = Q*invN - mean*mean;
    float scale = (float)((double)g[c] / sqrt(var + 1e-5));
    g_bn2[c] = scale;
    g_bn2[4 + c] = be[c] - (float)mean * scale;
  }
}

// ---------------- K3: BN1+ReLU + conv2 (16->4, k4 s2 p1) + BN2 partials ----------------
// grid (2,2,64), block (32,8). 32x32 t2 tile, per-channel staged input.
__global__ void k_conv2(const float* __restrict__ w2, const float* __restrict__ b2){
  __shared__ float s_in[66*68];
  __shared__ float s_w2[1024];
  __shared__ float s_bn[32];
  __shared__ float s_red[8*8];
  const int bz = blockIdx.z;
  const int ox0 = blockIdx.x*32, oy0 = blockIdx.y*32;
  const int ty = threadIdx.y, tx = threadIdx.x;
  const int tid = ty*32 + tx;
  for (int j = tid; j < 1024; j += 256) s_w2[j] = w2[j];
  if (tid < 32) s_bn[tid] = g_bn1[tid];
  float acc[4][4];
#pragma unroll
  for (int o = 0; o < 4; o++){
    float bo = b2[o];
#pragma unroll
    for (int k = 0; k < 4; k++) acc[o][k] = bo;
  }
  const float* t1b = g_t1 + (size_t)bz*262144;
  for (int c = 0; c < 16; c++){
    __syncthreads();
    float sc = s_bn[c], sh = s_bn[16+c];
    const float* inp = t1b + c*16384;
    for (int j = tid; j < 66*66; j += 256){
      int r = j/66, cc = j - r*66;
      int gr = 2*oy0 - 1 + r, gc = 2*ox0 - 1 + cc;
      float v = 0.f;
      if ((unsigned)gr < 128u && (unsigned)gc < 128u)
        v = fmaxf(fmaf(inp[gr*128 + gc], sc, sh), 0.f);
      s_in[r*68 + cc] = v;
    }
    __syncthreads();
#pragma unroll
    for (int ky = 0; ky < 4; ky++){
      float wk[4][4];
#pragma unroll
      for (int o = 0; o < 4; o++)
#pragma unroll
        for (int kx = 0; kx < 4; kx++)
          wk[o][kx] = s_w2[((o*16 + c)*4 + ky)*4 + kx];
#pragma unroll
      for (int k = 0; k < 4; k++){
        int rb = (2*(ty + 8*k) + ky)*68 + 2*tx;
        float2 va = *(const float2*)&s_in[rb];
        float2 vb = *(const float2*)&s_in[rb + 2];
#pragma unroll
        for (int o = 0; o < 4; o++){
          acc[o][k] = fmaf(va.x, wk[o][0], acc[o][k]);
          acc[o][k] = fmaf(va.y, wk[o][1], acc[o][k]);
          acc[o][k] = fmaf(vb.x, wk[o][2], acc[o][k]);
          acc[o][k] = fmaf(vb.y, wk[o][3], acc[o][k]);
        }
      }
    }
  }
  float st8[8];
#pragma unroll
  for (int v = 0; v < 8; v++) st8[v] = 0.f;
  float* outb = g_t2 + bz*16384;
#pragma unroll
  for (int k = 0; k < 4; k++){
    int off = (oy0 + ty + 8*k)*64 + ox0 + tx;
#pragma unroll
    for (int o = 0; o < 4; o++){
      float a = acc[o][k];
      outb[o*4096 + off] = a;
      st8[o] += a;
      st8[4+o] = fmaf(a, a, st8[4+o]);
    }
  }
  int lane = tid & 31, warp = tid >> 5;
#pragma unroll
  for (int v = 0; v < 8; v++){
    float r = warp_sum(st8[v]);
    if (lane == 0) s_red[warp*8 + v] = r;
  }
  __syncthreads();
  if (tid < 8){
    float t = 0.f;
#pragma unroll
    for (int w = 0; w < 8; w++) t += s_red[w*8 + tid];
    int blk = (bz*2 + blockIdx.y)*2 + blockIdx.x;
    g_partC[blk*8 + tid] = t;
  }
}

// ---------------- K5: BN2+ReLU + pre1x1 + VQ + loss + post1x1 ----------------
__global__ void k_vq(const float* __restrict__ wpre, const float* __restrict__ bpre,
                     const float* __restrict__ emb,
                     const float* __restrict__ wpost, const float* __restrict__ bpost){
  __shared__ float s_e[128];
  __shared__ float s_ee[64];
  __shared__ float s_red[8];
  int tid = threadIdx.x;
  if (tid < 128) s_e[tid] = emb[tid];
  __syncthreads();
  if (tid < 64) s_ee[tid] = s_e[2*tid]*s_e[2*tid] + s_e[2*tid+1]*s_e[2*tid+1];
  __syncthreads();
  int i = blockIdx.x*256 + tid;
  int b = i >> 12, p = i & 4095;
  const float* tb = g_t2 + b*16384 + p;
  float h0 = fmaxf(fmaf(tb[0],     g_bn2[0], g_bn2[4]), 0.f);
  float h1 = fmaxf(fmaf(tb[4096],  g_bn2[1], g_bn2[5]), 0.f);
  float h2 = fmaxf(fmaf(tb[8192],  g_bn2[2], g_bn2[6]), 0.f);
  float h3 = fmaxf(fmaf(tb[12288], g_bn2[3], g_bn2[7]), 0.f);
  float z0 = bpre[0] + wpre[0]*h0 + wpre[1]*h1 + wpre[2]*h2 + wpre[3]*h3;
  float z1 = bpre[1] + wpre[4]*h0 + wpre[5]*h1 + wpre[6]*h2 + wpre[7]*h3;
  float zz = z0*z0 + z1*z1;
  float best = 3.402823466e38f; int bi = 0;
  for (int k = 0; k < 64; k++){
    float d = zz - 2.f*(z0*s_e[2*k] + z1*s_e[2*k+1]) + s_ee[k];
    if (d < best){ best = d; bi = k; }
  }
  float q0 = s_e[2*bi], q1 = s_e[2*bi+1];
  float l = (q0 - z0)*(q0 - z0) + (q1 - z1)*(q1 - z1);
  float qs0 = z0 + (q0 - z0), qs1 = z1 + (q1 - z1);
  float* db = g_di + b*16384 + p;
#pragma unroll
  for (int o = 0; o < 4; o++)
    db[o*4096] = bpost[o] + wpost[2*o]*qs0 + wpost[2*o+1]*qs1;
  int lane = tid & 31, warp = tid >> 5;
  float r = warp_sum(l);
  if (lane == 0) s_red[warp] = r;
  __syncthreads();
  if (tid == 0){
    float t = 0.f;
#pragma unroll
    for (int w = 0; w < 8; w++) t += s_red[w];
    g_partE[blockIdx.x] = t;
  }
}

// ---------------- K6: convT1 (4->16, k4 s2 p1) + store t3 + BN3 partials ----------------
// grid (4,4,64), block (32,16). warp = oc, lane = column, rolling-register row walk.
__global__ void k_convt1(const float* __restrict__ wd1, const float* __restrict__ bd1){
  __shared__ float s_in[4*324];
  const int bz = blockIdx.z;
  const int ox0 = blockIdx.x*32, oy0 = blockIdx.y*32;
  const int oc = threadIdx.y, tx = threadIdx.x;
  const int tid = oc*32 + tx;
  const int kxA = (tx & 1) ? 2 : 3;
  const int kxB = (tx & 1) ? 0 : 1;
  float wA[4][4], wB[4][4];
#pragma unroll
  for (int c = 0; c < 4; c++)
#pragma unroll
    for (int ky = 0; ky < 4; ky++){
      wA[c][ky] = wd1[c*256 + oc*16 + ky*4 + kxA];
      wB[c][ky] = wd1[c*256 + oc*16 + ky*4 + kxB];
    }
  const float bb = bd1[oc];
  const int iyb = oy0/2 - 1, ixb = ox0/2 - 1;
  const float* inb = g_di + bz*16384;
  for (int j = tid; j < 1296; j += 512){
    int c = j/324, rem = j - c*324, r = rem/18, cc = rem - r*18;
    int iy = iyb + r, ix = ixb + cc;
    float v = 0.f;
    if ((unsigned)iy < 64u && (unsigned)ix < 64u) v = inb[c*4096 + iy*64 + ix];
    s_in[c*324 + rem] = v;
  }
  __syncthreads();
  const int lx = ((tx + 1) >> 1) + 1;
  float s = 0.f, q = 0.f;
  float* ob = g_t3 + (size_t)bz*262144 + (size_t)oc*16384 + oy0*128 + ox0 + tx;
  float pA0[4], pA1[4];
#pragma unroll
  for (int c = 0; c < 4; c++){
    pA0[c] = s_in[c*324 + 0*18 + lx-1];
    pA1[c] = s_in[c*324 + 0*18 + lx];
  }
  for (int a = 0; a <= 16; a++){
    int ly = a + 1;
    float pB0[4], pB1[4];
#pragma unroll
    for (int c = 0; c < 4; c++){
      pB0[c] = s_in[c*324 + ly*18 + lx-1];
      pB1[c] = s_in[c*324 + ly*18 + lx];
    }
    float accO = bb, accE = bb;
#pragma unroll
    for (int c = 0; c < 4; c++){
      accO = fmaf(pA0[c], wA[c][2], accO);
      accO = fmaf(pA1[c], wB[c][2], accO);
      accO = fmaf(pB0[c], wA[c][0], accO);
      accO = fmaf(pB1[c], wB[c][0], accO);
      accE = fmaf(pA0[c], wA[c][3], accE);
      accE = fmaf(pA1[c], wB[c][3], accE);
      accE = fmaf(pB0[c], wA[c][1], accE);
      accE = fmaf(pB1[c], wB[c][1], accE);
    }
    if (a >= 1){
      ob[(2*a - 1)*128] = accO;
      s += accO; q = fmaf(accO, accO, q);
    }
    if (a <= 15){
      ob[(2*a)*128] = accE;
      s += accE; q = fmaf(accE, accE, q);
    }
#pragma unroll
    for (int c = 0; c < 4; c++){ pA0[c] = pB0[c]; pA1[c] = pB1[c]; }
  }
  s = warp_sum(s); q = warp_sum(q);
  if (tx == 0){
    int blk = (bz*4 + blockIdx.y)*4 + blockIdx.x;
    g_partF[blk*32 + oc] = s;
    g_partF[blk*32 + 16 + oc] = q;
  }
}

// ---------------- K8: BN3+ReLU + convT2 (16->1) + tanh + recon partials ----------------
// grid (8,8,64), block (32,8). Channel-contiguous smem (stride 20) -> LDS.128 x4 per tap.
__global__ void k_convt2(const float* __restrict__ x, const float* __restrict__ wd2,
                         const float* __restrict__ bd2, float* __restrict__ out){
  __shared__ __align__(16) float s_t3[324*20];
  __shared__ float s_w[256];
  __shared__ float s_bn[32];
  __shared__ float s_red[8];
  const int bz = blockIdx.z;
  const int ox0 = blockIdx.x*32, oy0 = blockIdx.y*32;
  const int ty = threadIdx.y, tx = threadIdx.x;
  const int tid = ty*32 + tx;
  s_w[tid] = wd2[tid];
  if (tid < 32) s_bn[tid] = g_bn3[tid];
  const float bd = bd2[0];
  __syncthreads();
  const int tyb = oy0/2 - 1, txb = ox0/2 - 1;
  const float* inb = g_t3 + (size_t)bz*262144;
  for (int j = tid; j < 16*324; j += 256){
    int c = j/324, rem = j - c*324, r = rem/18, cc = rem - r*18;
    int iy = tyb + r, ix = txb + cc;
    float v = 0.f;
    if ((unsigned)iy < 128u && (unsigned)ix < 128u)
      v = fmaxf(fmaf(inb[c*16384 + iy*128 + ix], s_bn[c], s_bn[16+c]), 0.f);
    s_t3[rem*20 + c] = v;
  }
  __syncthreads();
  const int kyA = (ty & 1) ? 2 : 3, kyB = (ty & 1) ? 0 : 1;
  const int kxA = (tx & 1) ? 2 : 3, kxB = (tx & 1) ? 0 : 1;
  float wAA[16], wAB[16], wBA[16], wBB[16];
#pragma unroll
  for (int c = 0; c < 16; c++){
    wAA[c] = s_w[c*16 + kyA*4 + kxA];
    wAB[c] = s_w[c*16 + kyA*4 + kxB];
    wBA[c] = s_w[c*16 + kyB*4 + kxA];
    wBB[c] = s_w[c*16 + kyB*4 + kxB];
  }
  const int lx = ((tx + 1) >> 1) + 1;
  const int ly0 = ((ty + 1) >> 1) + 1;
  const float* xb = x + (size_t)bz*65536;
  float* ob = out + (size_t)bz*65536;
  float lsum = 0.f;
#pragma unroll
  for (int k = 0; k < 4; k++){
    int ly = ly0 + 4*k;
    const float4* qAA = (const float4*)(s_t3 + ((ly-1)*18 + lx-1)*20);
    const float4* qAB = (const float4*)(s_t3 + ((ly-1)*18 + lx  )*20);
    const float4* qBA = (const float4*)(s_t3 + ( ly   *18 + lx-1)*20);
    const float4* qBB = (const float4*)(s_t3 + ( ly   *18 + lx  )*20);
    float a0 = 0.f, a1 = 0.f, a2 = 0.f, a3 = 0.f;
#pragma unroll
    for (int g4 = 0; g4 < 4; g4++){
      float4 vAA = qAA[g4];
      float4 vAB = qAB[g4];
      float4 vBA = qBA[g4];
      float4 vBB = qBB[g4];
      const float* wa = wAA + g4*4;
      const float* wb = wAB + g4*4;
      const float* wc = wBA + g4*4;
      const float* wd = wBB + g4*4;
      a0 = fmaf(vAA.x, wa[0], a0); a0 = fmaf(vAA.y, wa[1], a0);
      a0 = fmaf(vAA.z, wa[2], a0); a0 = fmaf(vAA.w, wa[3], a0);
      a1 = fmaf(vAB.x, wb[0], a1); a1 = fmaf(vAB.y, wb[1], a1);
      a1 = fmaf(vAB.z, wb[2], a1); a1 = fmaf(vAB.w, wb[3], a1);
      a2 = fmaf(vBA.x, wc[0], a2); a2 = fmaf(vBA.y, wc[1], a2);
      a2 = fmaf(vBA.z, wc[2], a2); a2 = fmaf(vBA.w, wc[3], a2);
      a3 = fmaf(vBB.x, wd[0], a3); a3 = fmaf(vBB.y, wd[1], a3);
      a3 = fmaf(vBB.z, wd[2], a3); a3 = fmaf(vBB.w, wd[3], a3);
    }
    float acc = bd + ((a0 + a1) + (a2 + a3));
    float o = tanhf(acc);
    int off = (oy0 + ty + 8*k)*256 + ox0 + tx;
    ob[off] = o;
    float d = xb[off] - o;
    lsum = fmaf(d, d, lsum);
  }
  int lane = tid & 31, warp = tid >> 5;
  float r = warp_sum(lsum);
  if (lane == 0) s_red[warp] = r;
  __syncthreads();
  if (tid == 0){
    float t = 0.f;
#pragma unroll
    for (int w = 0; w < 8; w++) t += s_red[w];
    int blk = (bz*8 + blockIdx.y)*8 + blockIdx.x;
    g_partH[blk] = t;
  }
}

// ---------------- K9: final loss scalar ----------------
__global__ void k_loss(float* __restrict__ out_loss){
  __shared__ double s_red[8];
  int tid = threadIdx.x;
  double e = 0.0, h = 0.0;
  for (int i = tid; i < 1024; i += 256) e += (double)g_partE[i];
  for (int i = tid; i < 4096; i += 256) h += (double)g_partH[i];
  double t = e*1.2/524288.0 + h/4194304.0;  // (codebook + 0.2*commit) + recon
  int lane = tid & 31, warp = tid >> 5;
#pragma unroll
  for (int o = 16; o > 0; o >>= 1) t += __shfl_down_sync(0xffffffffu, t, o);
  if (lane == 0) s_red[warp] = t;
  __syncthreads();
  if (tid == 0){
    double s = 0.0;
    for (int w = 0; w < 8; w++) s += s_red[w];
    out_loss[0] = (float)s;
  }
}

// ---------------- launch ----------------
extern "C" void kernel_launch(void* const* d_in, const int* in_sizes, int n_in,
                              void* d_out, int out_size){
  const float* x    = (const float*)d_in[0];
  const float* w1   = (const float*)d_in[1];
  const float* b1   = (const float*)d_in[2];
  const float* g1   = (const float*)d_in[3];
  const float* be1  = (const float*)d_in[4];
  const float* w2   = (const float*)d_in[5];
  const float* b2   = (const float*)d_in[6];
  const float* g2   = (const float*)d_in[7];
  const float* be2  = (const float*)d_in[8];
  const float* wpre = (const float*)d_in[9];
  const float* bpre = (const float*)d_in[10];
  const float* emb  = (const float*)d_in[11];
  const float* wpost= (const float*)d_in[12];
  const float* bpost= (const float*)d_in[13];
  const float* wd1  = (const float*)d_in[14];
  const float* bd1  = (const float*)d_in[15];
  const float* g3   = (const float*)d_in[16];
  const float* be3  = (const float*)d_in[17];
  const float* wd2  = (const float*)d_in[18];
  const float* bd2  = (const float*)d_in[19];
  float* out = (float*)d_out;

  k_conv1  <<<dim3(4,4,64), dim3(32,8)>>>(x, w1, b1);
  k_bnfin32<<<16,256>>>(0, g1, be1);
  k_conv2  <<<dim3(2,2,64), dim3(32,8)>>>(w2, b2);
  k_bnfinC <<<4,256>>>(g2, be2);
  k_vq     <<<1024,256>>>(wpre, bpre, emb, wpost, bpost);
  k_convt1 <<<dim3(4,4,64), dim3(32,16)>>>(wd1, bd1);
  k_bnfin32<<<16,256>>>(1, g3, be3);
  k_convt2 <<<dim3(8,8,64), dim3(32,8)>>>(x, wd2, bd2, out);
  k_loss   <<<1,256>>>(out + (out_size - 1));
}

// round 14
// speedup vs baseline: 1.4261x; 1.0028x over previous
#include <cuda_runtime.h>
#include <math.h>

// ---------------- scratch (device globals; no allocation) ----------------
__device__ float g_t1[64*16*128*128];   // conv1 raw out
__device__ float g_t3[64*16*128*128];   // convT1 raw out
__device__ float g_t2[64*4*64*64];      // conv2 out
__device__ float g_di[64*4*64*64];      // post-VQ 1x1 out
__device__ float g_partA[1024*32];
__device__ float g_partF[1024*32];
__device__ float g_partC[512*8];
__device__ float g_partE[1024];
__device__ float g_partH[4096];
__device__ float g_bn1[32];  // scale[16], shift[16]
__device__ float g_bn3[32];

__device__ __forceinline__ float warp_sum(float v){
#pragma unroll
  for (int o = 16; o > 0; o >>= 1) v += __shfl_down_sync(0xffffffffu, v, o);
  return v;
}

// ---------------- K1: conv1 (1->16, k4 s2 p1) + store t1 + BN1 partials ----------------
// grid (4,4,64), block (32,8). warp = oc pair, lane = column, walk 32 rows.
__global__ void k_conv1(const float* __restrict__ x, const float* __restrict__ w1,
                        const float* __restrict__ b1){
  __shared__ float s_in[66*68];
  const int bz = blockIdx.z;
  const int ox0 = blockIdx.x*32, oy0 = blockIdx.y*32;
  const int w = threadIdx.y, tx = threadIdx.x;
  const int tid = w*32 + tx;
  const int oc0 = 2*w, oc1 = 2*w + 1;
  float wr0[16], wr1[16];
#pragma unroll
  for (int j = 0; j < 16; j++){ wr0[j] = w1[oc0*16 + j]; wr1[j] = w1[oc1*16 + j]; }
  const float bb0 = b1[oc0], bb1 = b1[oc1];
  const float* xb = x + (size_t)bz*65536;
  for (int j = tid; j < 66*66; j += 256){
    int r = j/66, c = j - r*66;
    int gr = oy0*2 - 1 + r, gc = ox0*2 - 1 + c;
    float v = 0.f;
    if ((unsigned)gr < 256u && (unsigned)gc < 256u) v = xb[gr*256 + gc];
    s_in[r*68 + c] = v;
  }
  __syncthreads();
  float s0 = 0.f, q0 = 0.f, s1 = 0.f, q1 = 0.f;
  float* o0 = g_t1 + (size_t)bz*262144 + (size_t)oc0*16384 + (oy0)*128 + ox0 + tx;
  float* o1 = o0 + 16384;
  float r0[4], r1[4];
  {
    float2 u0 = *(const float2*)&s_in[0*68 + 2*tx];
    float2 u1 = *(const float2*)&s_in[0*68 + 2*tx + 2];
    float2 v0 = *(const float2*)&s_in[1*68 + 2*tx];
    float2 v1 = *(const float2*)&s_in[1*68 + 2*tx + 2];
    r0[0]=u0.x; r0[1]=u0.y; r0[2]=u1.x; r0[3]=u1.y;
    r1[0]=v0.x; r1[1]=v0.y; r1[2]=v1.x; r1[3]=v1.y;
  }
#pragma unroll 4
  for (int y = 0; y < 32; y++){
    float r2[4], r3[4];
    {
      float2 u0 = *(const float2*)&s_in[(2*y+2)*68 + 2*tx];
      float2 u1 = *(const float2*)&s_in[(2*y+2)*68 + 2*tx + 2];
      float2 v0 = *(const float2*)&s_in[(2*y+3)*68 + 2*tx];
      float2 v1 = *(const float2*)&s_in[(2*y+3)*68 + 2*tx + 2];
      r2[0]=u0.x; r2[1]=u0.y; r2[2]=u1.x; r2[3]=u1.y;
      r3[0]=v0.x; r3[1]=v0.y; r3[2]=v1.x; r3[3]=v1.y;
    }
    float a0 = bb0, a1 = bb1;
#pragma unroll
    for (int j = 0; j < 4; j++){
      a0 = fmaf(r0[j], wr0[j],    a0);  a1 = fmaf(r0[j], wr1[j],    a1);
      a0 = fmaf(r1[j], wr0[4+j],  a0);  a1 = fmaf(r1[j], wr1[4+j],  a1);
      a0 = fmaf(r2[j], wr0[8+j],  a0);  a1 = fmaf(r2[j], wr1[8+j],  a1);
      a0 = fmaf(r3[j], wr0[12+j], a0);  a1 = fmaf(r3[j], wr1[12+j], a1);
    }
    o0[y*128] = a0;  o1[y*128] = a1;
    s0 += a0; q0 = fmaf(a0, a0, q0);
    s1 += a1; q1 = fmaf(a1, a1, q1);
#pragma unroll
    for (int j = 0; j < 4; j++){ r0[j] = r2[j]; r1[j] = r3[j]; }
  }
  s0 = warp_sum(s0); q0 = warp_sum(q0);
  s1 = warp_sum(s1); q1 = warp_sum(q1);
  if (tx == 0){
    int blk = (bz*4 + blockIdx.y)*4 + blockIdx.x;
    g_partA[blk*32 + oc0] = s0;
    g_partA[blk*32 + oc1] = s1;
    g_partA[blk*32 + 16 + oc0] = q0;
    g_partA[blk*32 + 16 + oc1] = q1;
  }
}

// ---------------- BN finalize for [1024][32] partials (BN1 / BN3) ----------------
__global__ void k_bnfin32(int which, const float* __restrict__ g, const float* __restrict__ be){
  const float* part = which ? g_partF : g_partA;
  float* bn = which ? g_bn3 : g_bn1;
  const int c = blockIdx.x;
  const int tid = threadIdx.x;
  double s = 0.0, q = 0.0;
  for (int i = tid; i < 1024; i += 256){
    s += (double)part[i*32 + c];
    q += (double)part[i*32 + 16 + c];
  }
#pragma unroll
  for (int o = 16; o > 0; o >>= 1){
    s += __shfl_down_sync(0xffffffffu, s, o);
    q += __shfl_down_sync(0xffffffffu, q, o);
  }
  __shared__ double ss[8], qq[8];
  int lane = tid & 31, warp = tid >> 5;
  if (lane == 0){ ss[warp] = s; qq[warp] = q; }
  __syncthreads();
  if (tid == 0){
    double S = 0.0, Q = 0.0;
#pragma unroll
    for (int w = 0; w < 8; w++){ S += ss[w]; Q += qq[w]; }
    const double invN = 1.0/1048576.0;
    double mean = S*invN;
    double var  = Q*invN - mean*mean;
    float scale = (float)((double)g[c] / sqrt(var + 1e-5));
    bn[c] = scale;
    bn[16 + c] = be[c] - (float)mean * scale;
  }
}

// ---------------- K3: BN1+ReLU + conv2 (16->4, k4 s2 p1) + BN2 partials ----------------
// grid (2,4,64), block (32,8). 32x16 t2 tile, double-buffered channel staging.
__global__ void k_conv2(const float* __restrict__ w2, const float* __restrict__ b2){
  __shared__ float s_in[2][34*68];
  __shared__ float s_w2[1024];
  __shared__ float s_bn[32];
  __shared__ float s_red[8*8];
  const int bz = blockIdx.z;
  const int ox0 = blockIdx.x*32, oy0 = blockIdx.y*16;
  const int ty = threadIdx.y, tx = threadIdx.x;
  const int tid = ty*32 + tx;
  for (int j = tid; j < 1024; j += 256) s_w2[j] = w2[j];
  if (tid < 32) s_bn[tid] = g_bn1[tid];
  __syncthreads();
  const float* t1b = g_t1 + (size_t)bz*262144;
  float acc[4][2];
#pragma unroll
  for (int o = 0; o < 4; o++){
    float bo = b2[o];
    acc[o][0] = bo; acc[o][1] = bo;
  }
  // stage channel 0 into buf 0
  {
    float sc = s_bn[0], sh = s_bn[16];
    const float* inp = t1b;
    for (int j = tid; j < 34*66; j += 256){
      int r = j/66, cc = j - r*66;
      int gr = 2*oy0 - 1 + r, gc = 2*ox0 - 1 + cc;
      float v = 0.f;
      if ((unsigned)gr < 128u && (unsigned)gc < 128u)
        v = fmaxf(fmaf(inp[gr*128 + gc], sc, sh), 0.f);
      s_in[0][r*68 + cc] = v;
    }
  }
  __syncthreads();
  for (int c = 0; c < 16; c++){
    const int cur = c & 1;
    if (c < 15){   // stage next channel into the other buffer (no sync needed yet)
      int cn = c + 1;
      float sc = s_bn[cn], sh = s_bn[16+cn];
      const float* inp = t1b + cn*16384;
      for (int j = tid; j < 34*66; j += 256){
        int r = j/66, cc = j - r*66;
        int gr = 2*oy0 - 1 + r, gc = 2*ox0 - 1 + cc;
        float v = 0.f;
        if ((unsigned)gr < 128u && (unsigned)gc < 128u)
          v = fmaxf(fmaf(inp[gr*128 + gc], sc, sh), 0.f);
        s_in[1 - cur][r*68 + cc] = v;
      }
    }
    const float* sp = s_in[cur];
#pragma unroll
    for (int ky = 0; ky < 4; ky++){
      float wk[4][4];
#pragma unroll
      for (int o = 0; o < 4; o++)
#pragma unroll
        for (int kx = 0; kx < 4; kx++)
          wk[o][kx] = s_w2[((o*16 + c)*4 + ky)*4 + kx];
#pragma unroll
      for (int k = 0; k < 2; k++){
        int rb = (2*(ty + 8*k) + ky)*68 + 2*tx;
        float2 va = *(const float2*)&sp[rb];
        float2 vb = *(const float2*)&sp[rb + 2];
#pragma unroll
        for (int o = 0; o < 4; o++){
          acc[o][k] = fmaf(va.x, wk[o][0], acc[o][k]);
          acc[o][k] = fmaf(va.y, wk[o][1], acc[o][k]);
          acc[o][k] = fmaf(vb.x, wk[o][2], acc[o][k]);
          acc[o][k] = fmaf(vb.y, wk[o][3], acc[o][k]);
        }
      }
    }
    __syncthreads();
  }
  float st8[8];
#pragma unroll
  for (int v = 0; v < 8; v++) st8[v] = 0.f;
  float* outb = g_t2 + bz*16384;
#pragma unroll
  for (int k = 0; k < 2; k++){
    int off = (oy0 + ty + 8*k)*64 + ox0 + tx;
#pragma unroll
    for (int o = 0; o < 4; o++){
      float a = acc[o][k];
      outb[o*4096 + off] = a;
      st8[o] += a;
      st8[4+o] = fmaf(a, a, st8[4+o]);
    }
  }
  int lane = tid & 31, warp = tid >> 5;
#pragma unroll
  for (int v = 0; v < 8; v++){
    float r = warp_sum(st8[v]);
    if (lane == 0) s_red[warp*8 + v] = r;
  }
  __syncthreads();
  if (tid < 8){
    float t = 0.f;
#pragma unroll
    for (int w = 0; w < 8; w++) t += s_red[w*8 + tid];
    int blk = (bz*4 + blockIdx.y)*2 + blockIdx.x;   // 0..511
    g_partC[blk*8 + tid] = t;
  }
}

// ---------------- K4: BN2(head-finalized) + ReLU + pre1x1 + VQ + loss + post1x1 ----------------
__global__ void k_vq(const float* __restrict__ g2, const float* __restrict__ be2,
                     const float* __restrict__ wpre, const float* __restrict__ bpre,
                     const float* __restrict__ emb,
                     const float* __restrict__ wpost, const float* __restrict__ bpost){
  __shared__ float s_e[128];
  __shared__ float s_ee[64];
  __shared__ float s_red[8];
  __shared__ float s_bn2[8];
  int tid = threadIdx.x;
  int lane = tid & 31, warp = tid >> 5;
  if (tid < 128) s_e[tid] = emb[tid];
  // BN2 head finalize: warp w (<4) handles channel w; 2KB read, fixed order.
  if (warp < 4){
    double s = 0.0, q = 0.0;
    for (int i = lane; i < 512; i += 32){
      s += (double)g_partC[i*8 + warp];
      q += (double)g_partC[i*8 + 4 + warp];
    }
#pragma unroll
    for (int o = 16; o > 0; o >>= 1){
      s += __shfl_down_sync(0xffffffffu, s, o);
      q += __shfl_down_sync(0xffffffffu, q, o);
    }
    if (lane == 0){
      const double invN = 1.0/262144.0;
      double mean = s*invN;
      double var  = q*invN - mean*mean;
      float scale = (float)((double)g2[warp] / sqrt(var + 1e-5));
      s_bn2[warp] = scale;
      s_bn2[4 + warp] = be2[warp] - (float)mean * scale;
    }
  }
  __syncthreads();
  if (tid < 64) s_ee[tid] = s_e[2*tid]*s_e[2*tid] + s_e[2*tid+1]*s_e[2*tid+1];
  __syncthreads();
  int i = blockIdx.x*256 + tid;
  int b = i >> 12, p = i & 4095;
  const float* tb = g_t2 + b*16384 + p;
  float h0 = fmaxf(fmaf(tb[0],     s_bn2[0], s_bn2[4]), 0.f);
  float h1 = fmaxf(fmaf(tb[4096],  s_bn2[1], s_bn2[5]), 0.f);
  float h2 = fmaxf(fmaf(tb[8192],  s_bn2[2], s_bn2[6]), 0.f);
  float h3 = fmaxf(fmaf(tb[12288], s_bn2[3], s_bn2[7]), 0.f);
  float z0 = bpre[0] + wpre[0]*h0 + wpre[1]*h1 + wpre[2]*h2 + wpre[3]*h3;
  float z1 = bpre[1] + wpre[4]*h0 + wpre[5]*h1 + wpre[6]*h2 + wpre[7]*h3;
  float zz = z0*z0 + z1*z1;
  float best = 3.402823466e38f; int bi = 0;
  for (int k = 0; k < 64; k++){
    float d = zz - 2.f*(z0*s_e[2*k] + z1*s_e[2*k+1]) + s_ee[k];
    if (d < best){ best = d; bi = k; }
  }
  float q0 = s_e[2*bi], q1 = s_e[2*bi+1];
  float l = (q0 - z0)*(q0 - z0) + (q1 - z1)*(q1 - z1);
  float qs0 = z0 + (q0 - z0), qs1 = z1 + (q1 - z1);
  float* db = g_di + b*16384 + p;
#pragma unroll
  for (int o = 0; o < 4; o++)
    db[o*4096] = bpost[o] + wpost[2*o]*qs0 + wpost[2*o+1]*qs1;
  float r = warp_sum(l);
  if (lane == 0) s_red[warp] = r;
  __syncthreads();
  if (tid == 0){
    float t = 0.f;
#pragma unroll
    for (int w = 0; w < 8; w++) t += s_red[w];
    g_partE[blockIdx.x] = t;
  }
}

// ---------------- K5: convT1 (4->16, k4 s2 p1) + store t3 + BN3 partials ----------------
// grid (4,4,64), block (32,16). warp = oc, lane = column, rolling-register row walk.
__global__ void k_convt1(const float* __restrict__ wd1, const float* __restrict__ bd1){
  __shared__ float s_in[4*324];
  const int bz = blockIdx.z;
  const int ox0 = blockIdx.x*32, oy0 = blockIdx.y*32;
  const int oc = threadIdx.y, tx = threadIdx.x;
  const int tid = oc*32 + tx;
  const int kxA = (tx & 1) ? 2 : 3;
  const int kxB = (tx & 1) ? 0 : 1;
  float wA[4][4], wB[4][4];
#pragma unroll
  for (int c = 0; c < 4; c++)
#pragma unroll
    for (int ky = 0; ky < 4; ky++){
      wA[c][ky] = wd1[c*256 + oc*16 + ky*4 + kxA];
      wB[c][ky] = wd1[c*256 + oc*16 + ky*4 + kxB];
    }
  const float bb = bd1[oc];
  const int iyb = oy0/2 - 1, ixb = ox0/2 - 1;
  const float* inb = g_di + bz*16384;
  for (int j = tid; j < 1296; j += 512){
    int c = j/324, rem = j - c*324, r = rem/18, cc = rem - r*18;
    int iy = iyb + r, ix = ixb + cc;
    float v = 0.f;
    if ((unsigned)iy < 64u && (unsigned)ix < 64u) v = inb[c*4096 + iy*64 + ix];
    s_in[c*324 + rem] = v;
  }
  __syncthreads();
  const int lx = ((tx + 1) >> 1) + 1;
  float s = 0.f, q = 0.f;
  float* ob = g_t3 + (size_t)bz*262144 + (size_t)oc*16384 + oy0*128 + ox0 + tx;
  float pA0[4], pA1[4];
#pragma unroll
  for (int c = 0; c < 4; c++){
    pA0[c] = s_in[c*324 + 0*18 + lx-1];
    pA1[c] = s_in[c*324 + 0*18 + lx];
  }
  for (int a = 0; a <= 16; a++){
    int ly = a + 1;
    float pB0[4], pB1[4];
#pragma unroll
    for (int c = 0; c < 4; c++){
      pB0[c] = s_in[c*324 + ly*18 + lx-1];
      pB1[c] = s_in[c*324 + ly*18 + lx];
    }
    float accO = bb, accE = bb;
#pragma unroll
    for (int c = 0; c < 4; c++){
      accO = fmaf(pA0[c], wA[c][2], accO);
      accO = fmaf(pA1[c], wB[c][2], accO);
      accO = fmaf(pB0[c], wA[c][0], accO);
      accO = fmaf(pB1[c], wB[c][0], accO);
      accE = fmaf(pA0[c], wA[c][3], accE);
      accE = fmaf(pA1[c], wB[c][3], accE);
      accE = fmaf(pB0[c], wA[c][1], accE);
      accE = fmaf(pB1[c], wB[c][1], accE);
    }
    if (a >= 1){
      ob[(2*a - 1)*128] = accO;
      s += accO; q = fmaf(accO, accO, q);
    }
    if (a <= 15){
      ob[(2*a)*128] = accE;
      s += accE; q = fmaf(accE, accE, q);
    }
#pragma unroll
    for (int c = 0; c < 4; c++){ pA0[c] = pB0[c]; pA1[c] = pB1[c]; }
  }
  s = warp_sum(s); q = warp_sum(q);
  if (tx == 0){
    int blk = (bz*4 + blockIdx.y)*4 + blockIdx.x;
    g_partF[blk*32 + oc] = s;
    g_partF[blk*32 + 16 + oc] = q;
  }
}

// ---------------- K7: BN3+ReLU + convT2 (16->1) + tanh + recon partials ----------------
// grid (8,8,64), block (32,8). Channel-contiguous smem (stride 20) -> LDS.128 x4 per tap.
__global__ void k_convt2(const float* __restrict__ x, const float* __restrict__ wd2,
                         const float* __restrict__ bd2, float* __restrict__ out){
  __shared__ __align__(16) float s_t3[324*20];
  __shared__ float s_w[256];
  __shared__ float s_bn[32];
  __shared__ float s_red[8];
  const int bz = blockIdx.z;
  const int ox0 = blockIdx.x*32, oy0 = blockIdx.y*32;
  const int ty = threadIdx.y, tx = threadIdx.x;
  const int tid = ty*32 + tx;
  s_w[tid] = wd2[tid];
  if (tid < 32) s_bn[tid] = g_bn3[tid];
  const float bd = bd2[0];
  __syncthreads();
  const int tyb = oy0/2 - 1, txb = ox0/2 - 1;
  const float* inb = g_t3 + (size_t)bz*262144;
  for (int j = tid; j < 16*324; j += 256){
    int c = j/324, rem = j - c*324, r = rem/18, cc = rem - r*18;
    int iy = tyb + r, ix = txb + cc;
    float v = 0.f;
    if ((unsigned)iy < 128u && (unsigned)ix < 128u)
      v = fmaxf(fmaf(inb[c*16384 + iy*128 + ix], s_bn[c], s_bn[16+c]), 0.f);
    s_t3[rem*20 + c] = v;
  }
  __syncthreads();
  const int kyA = (ty & 1) ? 2 : 3, kyB = (ty & 1) ? 0 : 1;
  const int kxA = (tx & 1) ? 2 : 3, kxB = (tx & 1) ? 0 : 1;
  float wAA[16], wAB[16], wBA[16], wBB[16];
#pragma unroll
  for (int c = 0; c < 16; c++){
    wAA[c] = s_w[c*16 + kyA*4 + kxA];
    wAB[c] = s_w[c*16 + kyA*4 + kxB];
    wBA[c] = s_w[c*16 + kyB*4 + kxA];
    wBB[c] = s_w[c*16 + kyB*4 + kxB];
  }
  const int lx = ((tx + 1) >> 1) + 1;
  const int ly0 = ((ty + 1) >> 1) + 1;
  const float* xb = x + (size_t)bz*65536;
  float* ob = out + (size_t)bz*65536;
  float lsum = 0.f;
#pragma unroll
  for (int k = 0; k < 4; k++){
    int ly = ly0 + 4*k;
    const float4* qAA = (const float4*)(s_t3 + ((ly-1)*18 + lx-1)*20);
    const float4* qAB = (const float4*)(s_t3 + ((ly-1)*18 + lx  )*20);
    const float4* qBA = (const float4*)(s_t3 + ( ly   *18 + lx-1)*20);
    const float4* qBB = (const float4*)(s_t3 + ( ly   *18 + lx  )*20);
    float a0 = 0.f, a1 = 0.f, a2 = 0.f, a3 = 0.f;
#pragma unroll
    for (int g4 = 0; g4 < 4; g4++){
      float4 vAA = qAA[g4];
      float4 vAB = qAB[g4];
      float4 vBA = qBA[g4];
      float4 vBB = qBB[g4];
      const float* wa = wAA + g4*4;
      const float* wb = wAB + g4*4;
      const float* wc = wBA + g4*4;
      const float* wd = wBB + g4*4;
      a0 = fmaf(vAA.x, wa[0], a0); a0 = fmaf(vAA.y, wa[1], a0);
      a0 = fmaf(vAA.z, wa[2], a0); a0 = fmaf(vAA.w, wa[3], a0);
      a1 = fmaf(vAB.x, wb[0], a1); a1 = fmaf(vAB.y, wb[1], a1);
      a1 = fmaf(vAB.z, wb[2], a1); a1 = fmaf(vAB.w, wb[3], a1);
      a2 = fmaf(vBA.x, wc[0], a2); a2 = fmaf(vBA.y, wc[1], a2);
      a2 = fmaf(vBA.z, wc[2], a2); a2 = fmaf(vBA.w, wc[3], a2);
      a3 = fmaf(vBB.x, wd[0], a3); a3 = fmaf(vBB.y, wd[1], a3);
      a3 = fmaf(vBB.z, wd[2], a3); a3 = fmaf(vBB.w, wd[3], a3);
    }
    float acc = bd + ((a0 + a1) + (a2 + a3));
    float o = tanhf(acc);
    int off = (oy0 + ty + 8*k)*256 + ox0 + tx;
    ob[off] = o;
    float d = xb[off] - o;
    lsum = fmaf(d, d, lsum);
  }
  int lane = tid & 31, warp = tid >> 5;
  float r = warp_sum(lsum);
  if (lane == 0) s_red[warp] = r;
  __syncthreads();
  if (tid == 0){
    float t = 0.f;
#pragma unroll
    for (int w = 0; w < 8; w++) t += s_red[w];
    int blk = (bz*8 + blockIdx.y)*8 + blockIdx.x;
    g_partH[blk] = t;
  }
}

// ---------------- K8: final loss scalar ----------------
__global__ void k_loss(float* __restrict__ out_loss){
  __shared__ double s_red[8];
  int tid = threadIdx.x;
  double e = 0.0, h = 0.0;
  for (int i = tid; i < 1024; i += 256) e += (double)g_partE[i];
  for (int i = tid; i < 4096; i += 256) h += (double)g_partH[i];
  double t = e*1.2/524288.0 + h/4194304.0;  // (codebook + 0.2*commit) + recon
  int lane = tid & 31, warp = tid >> 5;
#pragma unroll
  for (int o = 16; o > 0; o >>= 1) t += __shfl_down_sync(0xffffffffu, t, o);
  if (lane == 0) s_red[warp] = t;
  __syncthreads();
  if (tid == 0){
    double s = 0.0;
    for (int w = 0; w < 8; w++) s += s_red[w];
    out_loss[0] = (float)s;
  }
}

// ---------------- launch ----------------
extern "C" void kernel_launch(void* const* d_in, const int* in_sizes, int n_in,
                              void* d_out, int out_size){
  const float* x    = (const float*)d_in[0];
  const float* w1   = (const float*)d_in[1];
  const float* b1   = (const float*)d_in[2];
  const float* g1   = (const float*)d_in[3];
  const float* be1  = (const float*)d_in[4];
  const float* w2   = (const float*)d_in[5];
  const float* b2   = (const float*)d_in[6];
  const float* g2   = (const float*)d_in[7];
  const float* be2  = (const float*)d_in[8];
  const float* wpre = (const float*)d_in[9];
  const float* bpre = (const float*)d_in[10];
  const float* emb  = (const float*)d_in[11];
  const float* wpost= (const float*)d_in[12];
  const float* bpost= (const float*)d_in[13];
  const float* wd1  = (const float*)d_in[14];
  const float* bd1  = (const float*)d_in[15];
  const float* g3   = (const float*)d_in[16];
  const float* be3  = (const float*)d_in[17];
  const float* wd2  = (const float*)d_in[18];
  const float* bd2  = (const float*)d_in[19];
  float* out = (float*)d_out;

  k_conv1  <<<dim3(4,4,64), dim3(32,8)>>>(x, w1, b1);
  k_bnfin32<<<16,256>>>(0, g1, be1);
  k_conv2  <<<dim3(2,4,64), dim3(32,8)>>>(w2, b2);
  k_vq     <<<1024,256>>>(g2, be2, wpre, bpre, emb, wpost, bpost);
  k_convt1 <<<dim3(4,4,64), dim3(32,16)>>>(wd1, bd1);
  k_bnfin32<<<16,256>>>(1, g3, be3);
  k_convt2 <<<dim3(8,8,64), dim3(32,8)>>>(x, wd2, bd2, out);
  k_loss   <<<1,256>>>(out + (out_size - 1));
}

// round 15
// speedup vs baseline: 1.4448x; 1.0131x over previous
#include <cuda_runtime.h>
#include <math.h>

// ---------------- scratch (device globals; no allocation) ----------------
__device__ float g_t1[64*16*128*128];   // conv1 raw out
__device__ float g_t3[64*16*128*128];   // convT1 raw out
__device__ float g_t2[64*4*64*64];      // conv2 out
__device__ float g_di[64*4*64*64];      // post-VQ 1x1 out
__device__ float g_partA[1024*32];
__device__ float g_partF[1024*32];
__device__ float g_partC[512*8];
__device__ float g_partE[512];
__device__ float g_partH[4096];
__device__ float g_bn1[32];  // scale[16], shift[16]
__device__ float g_bn3[32];

__device__ __forceinline__ float warp_sum(float v){
#pragma unroll
  for (int o = 16; o > 0; o >>= 1) v += __shfl_down_sync(0xffffffffu, v, o);
  return v;
}

// ---------------- K1: conv1 (1->16, k4 s2 p1) + store t1 + BN1 partials ----------------
// grid (4,4,64), block (32,8). warp = oc pair, lane = column, walk 32 rows.
__global__ void k_conv1(const float* __restrict__ x, const float* __restrict__ w1,
                        const float* __restrict__ b1){
  __shared__ float s_in[66*68];
  const int bz = blockIdx.z;
  const int ox0 = blockIdx.x*32, oy0 = blockIdx.y*32;
  const int w = threadIdx.y, tx = threadIdx.x;
  const int tid = w*32 + tx;
  const int oc0 = 2*w, oc1 = 2*w + 1;
  float wr0[16], wr1[16];
#pragma unroll
  for (int j = 0; j < 16; j++){ wr0[j] = w1[oc0*16 + j]; wr1[j] = w1[oc1*16 + j]; }
  const float bb0 = b1[oc0], bb1 = b1[oc1];
  const float* xb = x + (size_t)bz*65536;
  for (int j = tid; j < 66*66; j += 256){
    int r = j/66, c = j - r*66;
    int gr = oy0*2 - 1 + r, gc = ox0*2 - 1 + c;
    float v = 0.f;
    if ((unsigned)gr < 256u && (unsigned)gc < 256u) v = xb[gr*256 + gc];
    s_in[r*68 + c] = v;
  }
  __syncthreads();
  float s0 = 0.f, q0 = 0.f, s1 = 0.f, q1 = 0.f;
  float* o0 = g_t1 + (size_t)bz*262144 + (size_t)oc0*16384 + (oy0)*128 + ox0 + tx;
  float* o1 = o0 + 16384;
  float r0[4], r1[4];
  {
    float2 u0 = *(const float2*)&s_in[0*68 + 2*tx];
    float2 u1 = *(const float2*)&s_in[0*68 + 2*tx + 2];
    float2 v0 = *(const float2*)&s_in[1*68 + 2*tx];
    float2 v1 = *(const float2*)&s_in[1*68 + 2*tx + 2];
    r0[0]=u0.x; r0[1]=u0.y; r0[2]=u1.x; r0[3]=u1.y;
    r1[0]=v0.x; r1[1]=v0.y; r1[2]=v1.x; r1[3]=v1.y;
  }
#pragma unroll 4
  for (int y = 0; y < 32; y++){
    float r2[4], r3[4];
    {
      float2 u0 = *(const float2*)&s_in[(2*y+2)*68 + 2*tx];
      float2 u1 = *(const float2*)&s_in[(2*y+2)*68 + 2*tx + 2];
      float2 v0 = *(const float2*)&s_in[(2*y+3)*68 + 2*tx];
      float2 v1 = *(const float2*)&s_in[(2*y+3)*68 + 2*tx + 2];
      r2[0]=u0.x; r2[1]=u0.y; r2[2]=u1.x; r2[3]=u1.y;
      r3[0]=v0.x; r3[1]=v0.y; r3[2]=v1.x; r3[3]=v1.y;
    }
    float a0 = bb0, a1 = bb1;
#pragma unroll
    for (int j = 0; j < 4; j++){
      a0 = fmaf(r0[j], wr0[j],    a0);  a1 = fmaf(r0[j], wr1[j],    a1);
      a0 = fmaf(r1[j], wr0[4+j],  a0);  a1 = fmaf(r1[j], wr1[4+j],  a1);
      a0 = fmaf(r2[j], wr0[8+j],  a0);  a1 = fmaf(r2[j], wr1[8+j],  a1);
      a0 = fmaf(r3[j], wr0[12+j], a0);  a1 = fmaf(r3[j], wr1[12+j], a1);
    }
    o0[y*128] = a0;  o1[y*128] = a1;
    s0 += a0; q0 = fmaf(a0, a0, q0);
    s1 += a1; q1 = fmaf(a1, a1, q1);
#pragma unroll
    for (int j = 0; j < 4; j++){ r0[j] = r2[j]; r1[j] = r3[j]; }
  }
  s0 = warp_sum(s0); q0 = warp_sum(q0);
  s1 = warp_sum(s1); q1 = warp_sum(q1);
  if (tx == 0){
    int blk = (bz*4 + blockIdx.y)*4 + blockIdx.x;
    g_partA[blk*32 + oc0] = s0;
    g_partA[blk*32 + oc1] = s1;
    g_partA[blk*32 + 16 + oc0] = q0;
    g_partA[blk*32 + 16 + oc1] = q1;
  }
}

// ---------------- BN finalize for [1024][32] partials (BN1 / BN3) ----------------
__global__ void k_bnfin32(int which, const float* __restrict__ g, const float* __restrict__ be){
  const float* part = which ? g_partF : g_partA;
  float* bn = which ? g_bn3 : g_bn1;
  const int c = blockIdx.x;
  const int tid = threadIdx.x;
  double s = 0.0, q = 0.0;
  for (int i = tid; i < 1024; i += 256){
    s += (double)part[i*32 + c];
    q += (double)part[i*32 + 16 + c];
  }
#pragma unroll
  for (int o = 16; o > 0; o >>= 1){
    s += __shfl_down_sync(0xffffffffu, s, o);
    q += __shfl_down_sync(0xffffffffu, q, o);
  }
  __shared__ double ss[8], qq[8];
  int lane = tid & 31, warp = tid >> 5;
  if (lane == 0){ ss[warp] = s; qq[warp] = q; }
  __syncthreads();
  if (tid == 0){
    double S = 0.0, Q = 0.0;
#pragma unroll
    for (int w = 0; w < 8; w++){ S += ss[w]; Q += qq[w]; }
    const double invN = 1.0/1048576.0;
    double mean = S*invN;
    double var  = Q*invN - mean*mean;
    float scale = (float)((double)g[c] / sqrt(var + 1e-5));
    bn[c] = scale;
    bn[16 + c] = be[c] - (float)mean * scale;
  }
}

// ---------------- K3: BN1+ReLU + conv2 (16->4, k4 s2 p1) + BN2 partials ----------------
// grid (2,4,64), block (32,8). 32x16 t2 tile, double-buffered channel staging.
__global__ void k_conv2(const float* __restrict__ w2, const float* __restrict__ b2){
  __shared__ float s_in[2][34*68];
  __shared__ float s_w2[1024];
  __shared__ float s_bn[32];
  __shared__ float s_red[8*8];
  const int bz = blockIdx.z;
  const int ox0 = blockIdx.x*32, oy0 = blockIdx.y*16;
  const int ty = threadIdx.y, tx = threadIdx.x;
  const int tid = ty*32 + tx;
  for (int j = tid; j < 1024; j += 256) s_w2[j] = w2[j];
  if (tid < 32) s_bn[tid] = g_bn1[tid];
  __syncthreads();
  const float* t1b = g_t1 + (size_t)bz*262144;
  float acc[4][2];
#pragma unroll
  for (int o = 0; o < 4; o++){
    float bo = b2[o];
    acc[o][0] = bo; acc[o][1] = bo;
  }
  {
    float sc = s_bn[0], sh = s_bn[16];
    const float* inp = t1b;
    for (int j = tid; j < 34*66; j += 256){
      int r = j/66, cc = j - r*66;
      int gr = 2*oy0 - 1 + r, gc = 2*ox0 - 1 + cc;
      float v = 0.f;
      if ((unsigned)gr < 128u && (unsigned)gc < 128u)
        v = fmaxf(fmaf(inp[gr*128 + gc], sc, sh), 0.f);
      s_in[0][r*68 + cc] = v;
    }
  }
  __syncthreads();
  for (int c = 0; c < 16; c++){
    const int cur = c & 1;
    if (c < 15){
      int cn = c + 1;
      float sc = s_bn[cn], sh = s_bn[16+cn];
      const float* inp = t1b + cn*16384;
      for (int j = tid; j < 34*66; j += 256){
        int r = j/66, cc = j - r*66;
        int gr = 2*oy0 - 1 + r, gc = 2*ox0 - 1 + cc;
        float v = 0.f;
        if ((unsigned)gr < 128u && (unsigned)gc < 128u)
          v = fmaxf(fmaf(inp[gr*128 + gc], sc, sh), 0.f);
        s_in[1 - cur][r*68 + cc] = v;
      }
    }
    const float* sp = s_in[cur];
#pragma unroll
    for (int ky = 0; ky < 4; ky++){
      float wk[4][4];
#pragma unroll
      for (int o = 0; o < 4; o++)
#pragma unroll
        for (int kx = 0; kx < 4; kx++)
          wk[o][kx] = s_w2[((o*16 + c)*4 + ky)*4 + kx];
#pragma unroll
      for (int k = 0; k < 2; k++){
        int rb = (2*(ty + 8*k) + ky)*68 + 2*tx;
        float2 va = *(const float2*)&sp[rb];
        float2 vb = *(const float2*)&sp[rb + 2];
#pragma unroll
        for (int o = 0; o < 4; o++){
          acc[o][k] = fmaf(va.x, wk[o][0], acc[o][k]);
          acc[o][k] = fmaf(va.y, wk[o][1], acc[o][k]);
          acc[o][k] = fmaf(vb.x, wk[o][2], acc[o][k]);
          acc[o][k] = fmaf(vb.y, wk[o][3], acc[o][k]);
        }
      }
    }
    __syncthreads();
  }
  float st8[8];
#pragma unroll
  for (int v = 0; v < 8; v++) st8[v] = 0.f;
  float* outb = g_t2 + bz*16384;
#pragma unroll
  for (int k = 0; k < 2; k++){
    int off = (oy0 + ty + 8*k)*64 + ox0 + tx;
#pragma unroll
    for (int o = 0; o < 4; o++){
      float a = acc[o][k];
      outb[o*4096 + off] = a;
      st8[o] += a;
      st8[4+o] = fmaf(a, a, st8[4+o]);
    }
  }
  int lane = tid & 31, warp = tid >> 5;
#pragma unroll
  for (int v = 0; v < 8; v++){
    float r = warp_sum(st8[v]);
    if (lane == 0) s_red[warp*8 + v] = r;
  }
  __syncthreads();
  if (tid < 8){
    float t = 0.f;
#pragma unroll
    for (int w = 0; w < 8; w++) t += s_red[w*8 + tid];
    int blk = (bz*4 + blockIdx.y)*2 + blockIdx.x;   // 0..511
    g_partC[blk*8 + tid] = t;
  }
}

// ---------------- K4: BN2(head-finalized) + ReLU + pre1x1 + VQ + loss + post1x1 ----------------
// grid 512, block 256. 2 pixels per thread; codes packed (-2e0,-2e1,ee,0) -> 1 LDS.128/code.
__global__ void k_vq(const float* __restrict__ g2, const float* __restrict__ be2,
                     const float* __restrict__ wpre, const float* __restrict__ bpre,
                     const float* __restrict__ emb,
                     const float* __restrict__ wpost, const float* __restrict__ bpost){
  __shared__ float s_e[128];
  __shared__ __align__(16) float4 s_pack[64];
  __shared__ float s_red[8];
  __shared__ float s_bn2[8];
  int tid = threadIdx.x;
  int lane = tid & 31, warp = tid >> 5;
  if (tid < 128) s_e[tid] = emb[tid];
  // BN2 head finalize: warp w (<4) handles channel w; fixed order.
  if (warp < 4){
    double s = 0.0, q = 0.0;
    for (int i = lane; i < 512; i += 32){
      s += (double)g_partC[i*8 + warp];
      q += (double)g_partC[i*8 + 4 + warp];
    }
#pragma unroll
    for (int o = 16; o > 0; o >>= 1){
      s += __shfl_down_sync(0xffffffffu, s, o);
      q += __shfl_down_sync(0xffffffffu, q, o);
    }
    if (lane == 0){
      const double invN = 1.0/262144.0;
      double mean = s*invN;
      double var  = q*invN - mean*mean;
      float scale = (float)((double)g2[warp] / sqrt(var + 1e-5));
      s_bn2[warp] = scale;
      s_bn2[4 + warp] = be2[warp] - (float)mean * scale;
    }
  }
  __syncthreads();
  if (tid < 64){
    float e0 = s_e[2*tid], e1 = s_e[2*tid+1];
    s_pack[tid] = make_float4(-2.f*e0, -2.f*e1, e0*e0 + e1*e1, 0.f);
  }
  __syncthreads();
  const float bn0 = s_bn2[0], bn1 = s_bn2[1], bn2c = s_bn2[2], bn3c = s_bn2[3];
  const float sh0 = s_bn2[4], sh1 = s_bn2[5], sh2 = s_bn2[6], sh3 = s_bn2[7];
  const float wp0 = wpre[0], wp1 = wpre[1], wp2 = wpre[2], wp3 = wpre[3];
  const float wp4 = wpre[4], wp5 = wpre[5], wp6 = wpre[6], wp7 = wpre[7];
  const float bp0 = bpre[0], bp1 = bpre[1];
  // two pixels: i and i+256 (same batch image: 512-pixel block within 4096-pixel image)
  int i0 = blockIdx.x*512 + tid;
  int b = i0 >> 12;
  int p0 = i0 & 4095, p1 = p0 + 256;
  const float* tb = g_t2 + b*16384;
  float z0a, z1a, z0b, z1b;
  {
    float h0 = fmaxf(fmaf(tb[p0],         bn0, sh0), 0.f);
    float h1 = fmaxf(fmaf(tb[4096 + p0],  bn1, sh1), 0.f);
    float h2 = fmaxf(fmaf(tb[8192 + p0],  bn2c, sh2), 0.f);
    float h3 = fmaxf(fmaf(tb[12288 + p0], bn3c, sh3), 0.f);
    z0a = bp0 + wp0*h0 + wp1*h1 + wp2*h2 + wp3*h3;
    z1a = bp1 + wp4*h0 + wp5*h1 + wp6*h2 + wp7*h3;
  }
  {
    float h0 = fmaxf(fmaf(tb[p1],         bn0, sh0), 0.f);
    float h1 = fmaxf(fmaf(tb[4096 + p1],  bn1, sh1), 0.f);
    float h2 = fmaxf(fmaf(tb[8192 + p1],  bn2c, sh2), 0.f);
    float h3 = fmaxf(fmaf(tb[12288 + p1], bn3c, sh3), 0.f);
    z0b = bp0 + wp0*h0 + wp1*h1 + wp2*h2 + wp3*h3;
    z1b = bp1 + wp4*h0 + wp5*h1 + wp6*h2 + wp7*h3;
  }
  float bestA = 3.402823466e38f, bestB = 3.402823466e38f;
  int biA = 0, biB = 0;
#pragma unroll 4
  for (int k = 0; k < 64; k++){
    float4 cd = s_pack[k];
    float dA = fmaf(cd.x, z0a, fmaf(cd.y, z1a, cd.z));   // d - |z|^2 (argmin-equivalent)
    float dB = fmaf(cd.x, z0b, fmaf(cd.y, z1b, cd.z));
    if (dA < bestA){ bestA = dA; biA = k; }
    if (dB < bestB){ bestB = dB; biB = k; }
  }
  float qa0 = s_e[2*biA], qa1 = s_e[2*biA+1];
  float qb0 = s_e[2*biB], qb1 = s_e[2*biB+1];
  float l = (qa0 - z0a)*(qa0 - z0a) + (qa1 - z1a)*(qa1 - z1a)
          + (qb0 - z0b)*(qb0 - z0b) + (qb1 - z1b)*(qb1 - z1b);
  float qsA0 = z0a + (qa0 - z0a), qsA1 = z1a + (qa1 - z1a);
  float qsB0 = z0b + (qb0 - z0b), qsB1 = z1b + (qb1 - z1b);
  float* db = g_di + b*16384;
#pragma unroll
  for (int o = 0; o < 4; o++){
    float w0 = wpost[2*o], w1 = wpost[2*o+1], bo = bpost[o];
    db[o*4096 + p0] = bo + w0*qsA0 + w1*qsA1;
    db[o*4096 + p1] = bo + w0*qsB0 + w1*qsB1;
  }
  float r = warp_sum(l);
  if (lane == 0) s_red[warp] = r;
  __syncthreads();
  if (tid == 0){
    float t = 0.f;
#pragma unroll
    for (int w = 0; w < 8; w++) t += s_red[w];
    g_partE[blockIdx.x] = t;
  }
}

// ---------------- K5: convT1 (4->16, k4 s2 p1) + store t3 + BN3 partials ----------------
// grid (4,4,64), block (32,16). warp = oc, lane = column, rolling-register row walk.
__global__ void k_convt1(const float* __restrict__ wd1, const float* __restrict__ bd1){
  __shared__ float s_in[4*324];
  const int bz = blockIdx.z;
  const int ox0 = blockIdx.x*32, oy0 = blockIdx.y*32;
  const int oc = threadIdx.y, tx = threadIdx.x;
  const int tid = oc*32 + tx;
  const int kxA = (tx & 1) ? 2 : 3;
  const int kxB = (tx & 1) ? 0 : 1;
  float wA[4][4], wB[4][4];
#pragma unroll
  for (int c = 0; c < 4; c++)
#pragma unroll
    for (int ky = 0; ky < 4; ky++){
      wA[c][ky] = wd1[c*256 + oc*16 + ky*4 + kxA];
      wB[c][ky] = wd1[c*256 + oc*16 + ky*4 + kxB];
    }
  const float bb = bd1[oc];
  const int iyb = oy0/2 - 1, ixb = ox0/2 - 1;
  const float* inb = g_di + bz*16384;
  for (int j = tid; j < 1296; j += 512){
    int c = j/324, rem = j - c*324, r = rem/18, cc = rem - r*18;
    int iy = iyb + r, ix = ixb + cc;
    float v = 0.f;
    if ((unsigned)iy < 64u && (unsigned)ix < 64u) v = inb[c*4096 + iy*64 + ix];
    s_in[c*324 + rem] = v;
  }
  __syncthreads();
  const int lx = ((tx + 1) >> 1) + 1;
  float s = 0.f, q = 0.f;
  float* ob = g_t3 + (size_t)bz*262144 + (size_t)oc*16384 + oy0*128 + ox0 + tx;
  float pA0[4], pA1[4];
#pragma unroll
  for (int c = 0; c < 4; c++){
    pA0[c] = s_in[c*324 + 0*18 + lx-1];
    pA1[c] = s_in[c*324 + 0*18 + lx];
  }
  for (int a = 0; a <= 16; a++){
    int ly = a + 1;
    float pB0[4], pB1[4];
#pragma unroll
    for (int c = 0; c < 4; c++){
      pB0[c] = s_in[c*324 + ly*18 + lx-1];
      pB1[c] = s_in[c*324 + ly*18 + lx];
    }
    float accO = bb, accE = bb;
#pragma unroll
    for (int c = 0; c < 4; c++){
      accO = fmaf(pA0[c], wA[c][2], accO);
      accO = fmaf(pA1[c], wB[c][2], accO);
      accO = fmaf(pB0[c], wA[c][0], accO);
      accO = fmaf(pB1[c], wB[c][0], accO);
      accE = fmaf(pA0[c], wA[c][3], accE);
      accE = fmaf(pA1[c], wB[c][3], accE);
      accE = fmaf(pB0[c], wA[c][1], accE);
      accE = fmaf(pB1[c], wB[c][1], accE);
    }
    if (a >= 1){
      ob[(2*a - 1)*128] = accO;
      s += accO; q = fmaf(accO, accO, q);
    }
    if (a <= 15){
      ob[(2*a)*128] = accE;
      s += accE; q = fmaf(accE, accE, q);
    }
#pragma unroll
    for (int c = 0; c < 4; c++){ pA0[c] = pB0[c]; pA1[c] = pB1[c]; }
  }
  s = warp_sum(s); q = warp_sum(q);
  if (tx == 0){
    int blk = (bz*4 + blockIdx.y)*4 + blockIdx.x;
    g_partF[blk*32 + oc] = s;
    g_partF[blk*32 + 16 + oc] = q;
  }
}

// ---------------- K7: BN3+ReLU + convT2 (16->1) + tanh + recon partials ----------------
// grid (8,8,64), block (32,8). Channel-contiguous smem (stride 20) -> LDS.128 x4 per tap.
__global__ void k_convt2(const float* __restrict__ x, const float* __restrict__ wd2,
                         const float* __restrict__ bd2, float* __restrict__ out){
  __shared__ __align__(16) float s_t3[324*20];
  __shared__ float s_w[256];
  __shared__ float s_bn[32];
  __shared__ float s_red[8];
  const int bz = blockIdx.z;
  const int ox0 = blockIdx.x*32, oy0 = blockIdx.y*32;
  const int ty = threadIdx.y, tx = threadIdx.x;
  const int tid = ty*32 + tx;
  s_w[tid] = wd2[tid];
  if (tid < 32) s_bn[tid] = g_bn3[tid];
  const float bd = bd2[0];
  __syncthreads();
  const int tyb = oy0/2 - 1, txb = ox0/2 - 1;
  const float* inb = g_t3 + (size_t)bz*262144;
  for (int j = tid; j < 16*324; j += 256){
    int c = j/324, rem = j - c*324, r = rem/18, cc = rem - r*18;
    int iy = tyb + r, ix = txb + cc;
    float v = 0.f;
    if ((unsigned)iy < 128u && (unsigned)ix < 128u)
      v = fmaxf(fmaf(inb[c*16384 + iy*128 + ix], s_bn[c], s_bn[16+c]), 0.f);
    s_t3[rem*20 + c] = v;
  }
  __syncthreads();
  const int kyA = (ty & 1) ? 2 : 3, kyB = (ty & 1) ? 0 : 1;
  const int kxA = (tx & 1) ? 2 : 3, kxB = (tx & 1) ? 0 : 1;
  float wAA[16], wAB[16], wBA[16], wBB[16];
#pragma unroll
  for (int c = 0; c < 16; c++){
    wAA[c] = s_w[c*16 + kyA*4 + kxA];
    wAB[c] = s_w[c*16 + kyA*4 + kxB];
    wBA[c] = s_w[c*16 + kyB*4 + kxA];
    wBB[c] = s_w[c*16 + kyB*4 + kxB];
  }
  const int lx = ((tx + 1) >> 1) + 1;
  const int ly0 = ((ty + 1) >> 1) + 1;
  const float* xb = x + (size_t)bz*65536;
  float* ob = out + (size_t)bz*65536;
  float lsum = 0.f;
#pragma unroll
  for (int k = 0; k < 4; k++){
    int ly = ly0 + 4*k;
    const float4* qAA = (const float4*)(s_t3 + ((ly-1)*18 + lx-1)*20);
    const float4* qAB = (const float4*)(s_t3 + ((ly-1)*18 + lx  )*20);
    const float4* qBA = (const float4*)(s_t3 + ( ly   *18 + lx-1)*20);
    const float4* qBB = (const float4*)(s_t3 + ( ly   *18 + lx  )*20);
    float a0 = 0.f, a1 = 0.f, a2 = 0.f, a3 = 0.f;
#pragma unroll
    for (int g4 = 0; g4 < 4; g4++){
      float4 vAA = qAA[g4];
      float4 vAB = qAB[g4];
      float4 vBA = qBA[g4];
      float4 vBB = qBB[g4];
      const float* wa = wAA + g4*4;
      const float* wb = wAB + g4*4;
      const float* wc = wBA + g4*4;
      const float* wd = wBB + g4*4;
      a0 = fmaf(vAA.x, wa[0], a0); a0 = fmaf(vAA.y, wa[1], a0);
      a0 = fmaf(vAA.z, wa[2], a0); a0 = fmaf(vAA.w, wa[3], a0);
      a1 = fmaf(vAB.x, wb[0], a1); a1 = fmaf(vAB.y, wb[1], a1);
      a1 = fmaf(vAB.z, wb[2], a1); a1 = fmaf(vAB.w, wb[3], a1);
      a2 = fmaf(vBA.x, wc[0], a2); a2 = fmaf(vBA.y, wc[1], a2);
      a2 = fmaf(vBA.z, wc[2], a2); a2 = fmaf(vBA.w, wc[3], a2);
      a3 = fmaf(vBB.x, wd[0], a3); a3 = fmaf(vBB.y, wd[1], a3);
      a3 = fmaf(vBB.z, wd[2], a3); a3 = fmaf(vBB.w, wd[3], a3);
    }
    float acc = bd + ((a0 + a1) + (a2 + a3));
    float o = tanhf(acc);
    int off = (oy0 + ty + 8*k)*256 + ox0 + tx;
    ob[off] = o;
    float d = xb[off] - o;
    lsum = fmaf(d, d, lsum);
  }
  int lane = tid & 31, warp = tid >> 5;
  float r = warp_sum(lsum);
  if (lane == 0) s_red[warp] = r;
  __syncthreads();
  if (tid == 0){
    float t = 0.f;
#pragma unroll
    for (int w = 0; w < 8; w++) t += s_red[w];
    int blk = (bz*8 + blockIdx.y)*8 + blockIdx.x;
    g_partH[blk] = t;
  }
}

// ---------------- K8: final loss scalar ----------------
__global__ void k_loss(float* __restrict__ out_loss){
  __shared__ double s_red[8];
  int tid = threadIdx.x;
  double e = 0.0, h = 0.0;
  for (int i = tid; i < 512; i += 256) e += (double)g_partE[i];
  for (int i = tid; i < 4096; i += 256) h += (double)g_partH[i];
  double t = e*1.2/524288.0 + h/4194304.0;  // (codebook + 0.2*commit) + recon
  int lane = tid & 31, warp = tid >> 5;
#pragma unroll
  for (int o = 16; o > 0; o >>= 1) t += __shfl_down_sync(0xffffffffu, t, o);
  if (lane == 0) s_red[warp] = t;
  __syncthreads();
  if (tid == 0){
    double s = 0.0;
    for (int w = 0; w < 8; w++) s += s_red[w];
    out_loss[0] = (float)s;
  }
}

// ---------------- launch ----------------
extern "C" void kernel_launch(void* const* d_in, const int* in_sizes, int n_in,
                              void* d_out, int out_size){
  const float* x    = (const float*)d_in[0];
  const float* w1   = (const float*)d_in[1];
  const float* b1   = (const float*)d_in[2];
  const float* g1   = (const float*)d_in[3];
  const float* be1  = (const float*)d_in[4];
  const float* w2   = (const float*)d_in[5];
  const float* b2   = (const float*)d_in[6];
  const float* g2   = (const float*)d_in[7];
  const float* be2  = (const float*)d_in[8];
  const float* wpre = (const float*)d_in[9];
  const float* bpre = (const float*)d_in[10];
  const float* emb  = (const float*)d_in[11];
  const float* wpost= (const float*)d_in[12];
  const float* bpost= (const float*)d_in[13];
  const float* wd1  = (const float*)d_in[14];
  const float* bd1  = (const float*)d_in[15];
  const float* g3   = (const float*)d_in[16];
  const float* be3  = (const float*)d_in[17];
  const float* wd2  = (const float*)d_in[18];
  const float* bd2  = (const float*)d_in[19];
  float* out = (float*)d_out;

  k_conv1  <<<dim3(4,4,64), dim3(32,8)>>>(x, w1, b1);
  k_bnfin32<<<16,256>>>(0, g1, be1);
  k_conv2  <<<dim3(2,4,64), dim3(32,8)>>>(w2, b2);
  k_vq     <<<512,256>>>(g2, be2, wpre, bpre, emb, wpost, bpost);
  k_convt1 <<<dim3(4,4,64), dim3(32,16)>>>(wd1, bd1);
  k_bnfin32<<<16,256>>>(1, g3, be3);
  k_convt2 <<<dim3(8,8,64), dim3(32,8)>>>(x, wd2, bd2, out);
  k_loss   <<<1,256>>>(out + (out_size - 1));
}